// round 2
// baseline (speedup 1.0000x reference)
#include <cuda_runtime.h>
#include <cuda_bf16.h>
#include <math.h>

#define B_   8
#define LQ_  2048
#define LK_  2048
#define D_   256
#define H_   128

typedef unsigned long long u64;

// Scratch (device globals: allocation-free per harness rules)
__device__ float g_pq[(size_t)B_ * LQ_ * H_];                 // relu(Q Wq^T)          [B,Lq,H]
__device__ float g_pk[(size_t)B_ * LK_ * H_];                 // relu(K Wk^T)*scaling  [B,Lk,H]
__device__ float g_S [(size_t)B_ * LQ_ * LK_];                // scores                [B,Lq,Lk]
__device__ float g_m1[B_ * LQ_], g_l1[B_ * LQ_];              // branch1 row stats (over k)
__device__ float g_m2[B_ * LK_], g_l2[B_ * LK_];              // branch2 col stats (over q)
__device__ unsigned char g_mask1[B_ * LK_];
__device__ unsigned char g_mask2[B_ * LQ_];
__device__ int g_mask_is_byte;

// packed fp32x2 FMA (SASS FFMA2): d = a*b + d, lanewise on both 32-bit halves
__device__ __forceinline__ void ffma2(u64& d, u64 a, u64 b) {
    asm("fma.rn.f32x2 %0, %1, %2, %0;" : "+l"(d) : "l"(a), "l"(b));
}
__device__ __forceinline__ float pairsum(u64 v) {
    float lo, hi;
    asm("mov.b64 {%0,%1}, %2;" : "=f"(lo), "=f"(hi) : "l"(v));
    return lo + hi;
}

// ---------------------------------------------------------------------------
// Mask dtype canonicalization (bool-as-byte vs int32)
// ---------------------------------------------------------------------------
__global__ void detect_mask_kernel(const unsigned char* m) {
    __shared__ int flag;
    if (threadIdx.x == 0) flag = 0;
    __syncthreads();
    for (int i = threadIdx.x; i < B_ * LK_; i += blockDim.x)
        if ((i & 3) && m[i]) flag = 1;
    __syncthreads();
    if (threadIdx.x == 0) g_mask_is_byte = flag;
}

__global__ void build_mask_kernel(const void* m1, const void* m2) {
    int i = blockIdx.x * blockDim.x + threadIdx.x;
    if (i >= B_ * LK_) return;
    if (g_mask_is_byte) {
        g_mask1[i] = ((const unsigned char*)m1)[i] ? 1 : 0;
        g_mask2[i] = ((const unsigned char*)m2)[i] ? 1 : 0;
    } else {
        g_mask1[i] = ((const int*)m1)[i] ? 1 : 0;
        g_mask2[i] = ((const int*)m2)[i] ? 1 : 0;
    }
}

// ---------------------------------------------------------------------------
// Projections: out[r,h] = relu(sum_d X[r,d] * W[h,d]) (* scaling[h] for pk)
// 128x128 block tile, 8x8 thread tile, f32x2 k-pair accumulators, K=256.
// ---------------------------------------------------------------------------
__global__ void __launch_bounds__(256) proj_kernel(
    const float* __restrict__ Q, const float* __restrict__ K,
    const float* __restrict__ Wq, const float* __restrict__ Wk,
    const float* __restrict__ scaling)
{
    __shared__ float2 As2[16][130];   // (k,k+1) pairs per row
    __shared__ float2 Bs2[16][130];

    const int which = blockIdx.y;
    const float* X = which ? K : Q;
    const float* W = which ? Wk : Wq;
    float* out = which ? g_pk : g_pq;
    const int row0 = blockIdx.x * 128;

    const int tid = threadIdx.x;
    const int tr8 = (tid >> 4) << 3;
    const int tc8 = (tid & 15) << 3;
    const int r0 = tid >> 3, h4 = tid & 7;

    u64 acc[8][8];
    #pragma unroll
    for (int i = 0; i < 8; i++)
        #pragma unroll
        for (int j = 0; j < 8; j++) acc[i][j] = 0ull;

    float4 pa[4], pb[4];
    #pragma unroll
    for (int t = 0; t < 4; t++) {
        pa[t] = *(const float4*)&X[(size_t)(row0 + r0 + 32 * t) * D_ + h4 * 4];
        pb[t] = *(const float4*)&W[(size_t)(r0 + 32 * t) * D_ + h4 * 4];
    }

    for (int k0 = 0; k0 < D_; k0 += 32) {
        #pragma unroll
        for (int t = 0; t < 4; t++) {
            int r = r0 + 32 * t;
            As2[h4 * 2][r]     = make_float2(pa[t].x, pa[t].y);
            As2[h4 * 2 + 1][r] = make_float2(pa[t].z, pa[t].w);
            Bs2[h4 * 2][r]     = make_float2(pb[t].x, pb[t].y);
            Bs2[h4 * 2 + 1][r] = make_float2(pb[t].z, pb[t].w);
        }
        __syncthreads();
        if (k0 + 32 < D_) {
            #pragma unroll
            for (int t = 0; t < 4; t++) {
                pa[t] = *(const float4*)&X[(size_t)(row0 + r0 + 32 * t) * D_ + k0 + 32 + h4 * 4];
                pb[t] = *(const float4*)&W[(size_t)(r0 + 32 * t) * D_ + k0 + 32 + h4 * 4];
            }
        }
        #pragma unroll
        for (int k2 = 0; k2 < 16; k2++) {
            u64 a2[8], b2[8];
            #pragma unroll
            for (int u = 0; u < 4; u++) {
                ulonglong2 ta = *(const ulonglong2*)&As2[k2][tr8 + 2 * u];
                a2[2 * u] = ta.x; a2[2 * u + 1] = ta.y;
                ulonglong2 tb = *(const ulonglong2*)&Bs2[k2][tc8 + 2 * u];
                b2[2 * u] = tb.x; b2[2 * u + 1] = tb.y;
            }
            #pragma unroll
            for (int i = 0; i < 8; i++)
                #pragma unroll
                for (int j = 0; j < 8; j++)
                    ffma2(acc[i][j], a2[i], b2[j]);
        }
        __syncthreads();
    }

    #pragma unroll
    for (int i = 0; i < 8; i++) {
        int r = row0 + tr8 + i;
        float v[8];
        #pragma unroll
        for (int j = 0; j < 8; j++) {
            v[j] = fmaxf(pairsum(acc[i][j]), 0.f);
            if (which) v[j] *= scaling[tc8 + j];
        }
        *(float4*)&out[(size_t)r * H_ + tc8]     = make_float4(v[0], v[1], v[2], v[3]);
        *(float4*)&out[(size_t)r * H_ + tc8 + 4] = make_float4(v[4], v[5], v[6], v[7]);
    }
}

// ---------------------------------------------------------------------------
// scores[b] = pq[b] @ pk[b]^T  (128x128 tile, 8x8 thread tile, f32x2)
// ---------------------------------------------------------------------------
__global__ void __launch_bounds__(256) scores_kernel()
{
    __shared__ float2 As2[16][130];
    __shared__ float2 Bs2[16][130];

    const int b = blockIdx.z;
    const int row0 = blockIdx.y * 128;
    const int col0 = blockIdx.x * 128;
    const float* A  = g_pq + (size_t)b * LQ_ * H_;
    const float* Bm = g_pk + (size_t)b * LK_ * H_;
    float* S = g_S + (size_t)b * LQ_ * LK_;

    const int tid = threadIdx.x;
    const int tr8 = (tid >> 4) << 3;
    const int tc8 = (tid & 15) << 3;
    const int r0 = tid >> 3, h4 = tid & 7;

    u64 acc[8][8];
    #pragma unroll
    for (int i = 0; i < 8; i++)
        #pragma unroll
        for (int j = 0; j < 8; j++) acc[i][j] = 0ull;

    float4 pa[4], pb[4];
    #pragma unroll
    for (int t = 0; t < 4; t++) {
        pa[t] = *(const float4*)&A [(size_t)(row0 + r0 + 32 * t) * H_ + h4 * 4];
        pb[t] = *(const float4*)&Bm[(size_t)(col0 + r0 + 32 * t) * H_ + h4 * 4];
    }

    for (int k0 = 0; k0 < H_; k0 += 32) {
        #pragma unroll
        for (int t = 0; t < 4; t++) {
            int r = r0 + 32 * t;
            As2[h4 * 2][r]     = make_float2(pa[t].x, pa[t].y);
            As2[h4 * 2 + 1][r] = make_float2(pa[t].z, pa[t].w);
            Bs2[h4 * 2][r]     = make_float2(pb[t].x, pb[t].y);
            Bs2[h4 * 2 + 1][r] = make_float2(pb[t].z, pb[t].w);
        }
        __syncthreads();
        if (k0 + 32 < H_) {
            #pragma unroll
            for (int t = 0; t < 4; t++) {
                pa[t] = *(const float4*)&A [(size_t)(row0 + r0 + 32 * t) * H_ + k0 + 32 + h4 * 4];
                pb[t] = *(const float4*)&Bm[(size_t)(col0 + r0 + 32 * t) * H_ + k0 + 32 + h4 * 4];
            }
        }
        #pragma unroll
        for (int k2 = 0; k2 < 16; k2++) {
            u64 a2[8], b2[8];
            #pragma unroll
            for (int u = 0; u < 4; u++) {
                ulonglong2 ta = *(const ulonglong2*)&As2[k2][tr8 + 2 * u];
                a2[2 * u] = ta.x; a2[2 * u + 1] = ta.y;
                ulonglong2 tb = *(const ulonglong2*)&Bs2[k2][tc8 + 2 * u];
                b2[2 * u] = tb.x; b2[2 * u + 1] = tb.y;
            }
            #pragma unroll
            for (int i = 0; i < 8; i++)
                #pragma unroll
                for (int j = 0; j < 8; j++)
                    ffma2(acc[i][j], a2[i], b2[j]);
        }
        __syncthreads();
    }

    #pragma unroll
    for (int i = 0; i < 8; i++) {
        float* orow = &S[(size_t)(row0 + tr8 + i) * LK_ + col0 + tc8];
        *(float4*)&orow[0] = make_float4(pairsum(acc[i][0]), pairsum(acc[i][1]),
                                         pairsum(acc[i][2]), pairsum(acc[i][3]));
        *(float4*)&orow[4] = make_float4(pairsum(acc[i][4]), pairsum(acc[i][5]),
                                         pairsum(acc[i][6]), pairsum(acc[i][7]));
    }
}

// ---------------------------------------------------------------------------
// Branch-1 stats: per (b,q): max & sum-exp over k (masked by g_mask1[b,k])
// ---------------------------------------------------------------------------
__global__ void __launch_bounds__(256) stats1_kernel()
{
    const int row = blockIdx.x;
    const int b = row >> 11;
    const float* Srow = g_S + (size_t)row * LK_;
    const unsigned char* mk = g_mask1 + (b << 11);
    const int tid = threadIdx.x;

    float vals[8];
    float m = -INFINITY;
    #pragma unroll
    for (int i = 0; i < 8; i++) {
        int k = tid + (i << 8);
        float s = Srow[k];
        vals[i] = mk[k] ? -INFINITY : s;
        m = fmaxf(m, vals[i]);
    }

    __shared__ float red[256];
    red[tid] = m;
    __syncthreads();
    for (int off = 128; off > 0; off >>= 1) {
        if (tid < off) red[tid] = fmaxf(red[tid], red[tid + off]);
        __syncthreads();
    }
    m = red[0];
    __syncthreads();

    float l = 0.f;
    #pragma unroll
    for (int i = 0; i < 8; i++) l += __expf(vals[i] - m);
    red[tid] = l;
    __syncthreads();
    for (int off = 128; off > 0; off >>= 1) {
        if (tid < off) red[tid] += red[tid + off];
        __syncthreads();
    }
    if (tid == 0) { g_m1[row] = m; g_l1[row] = red[0]; }
}

// ---------------------------------------------------------------------------
// Branch-2 stats: per (b,k): max & sum-exp over q (masked by g_mask2[b,q]).
// Two clean passes (no online rescale, no divergence).
// ---------------------------------------------------------------------------
__global__ void __launch_bounds__(256) stats2_kernel()
{
    const int b = blockIdx.y;
    const int k0 = blockIdx.x * 64;
    const int tid = threadIdx.x;
    const int kk = tid & 63, qg = tid >> 6;
    const float* Sb = g_S + (size_t)b * LQ_ * LK_;
    const unsigned char* mk = g_mask2 + (b << 11);

    float m = -INFINITY;
    #pragma unroll 8
    for (int q = qg; q < LQ_; q += 4) {
        float s = Sb[(size_t)q * LK_ + k0 + kk];
        m = fmaxf(m, mk[q] ? -INFINITY : s);
    }
    __shared__ float sm[256];
    sm[tid] = m;
    __syncthreads();
    if (tid < 64)
        sm[tid] = fmaxf(fmaxf(sm[tid], sm[tid + 64]), fmaxf(sm[tid + 128], sm[tid + 192]));
    __syncthreads();
    m = sm[kk];

    float l = 0.f;
    #pragma unroll 8
    for (int q = qg; q < LQ_; q += 4) {
        float s = Sb[(size_t)q * LK_ + k0 + kk];
        l += mk[q] ? 0.f : __expf(s - m);
    }
    __shared__ float sl[256];
    sl[tid] = l;
    __syncthreads();
    if (tid < 64) {
        l = sl[tid] + sl[tid + 64] + sl[tid + 128] + sl[tid + 192];
        g_m2[(b << 11) + k0 + tid] = sm[tid];
        g_l2[(b << 11) + k0 + tid] = l;
    }
}

// ---------------------------------------------------------------------------
// Fused softmax-weighted GEMM, both branches, 128x128 tile, f32x2 k-pair.
//   br=0: out1[q,d] = il1[q] * sum_k !m1[k]*exp(S[q,k]-m1[q]) * V1[k,d]
//   br=1: out2[k,d] = il2[k] * sum_q !m2[q]*exp(S[q,k]-m2[k]) * V2[q,d]
// ---------------------------------------------------------------------------
__global__ void __launch_bounds__(256) branch_kernel(
    const float* __restrict__ V1, const float* __restrict__ V2,
    float* __restrict__ out)
{
    __shared__ float2 ws2[16][130];
    __shared__ float2 vs2[16][130];
    __shared__ float s_m[128], s_sc[128];

    const int zz = blockIdx.z;
    const int br = zz & 1, b = zz >> 1;
    const int row0 = blockIdx.y * 128;
    const int col0 = blockIdx.x * 128;

    const float* V = (br ? V2 : V1) + (size_t)b * 2048 * D_;
    const unsigned char* mk = (br ? g_mask2 : g_mask1) + (b << 11);
    const float* Sb = g_S + (size_t)b * LQ_ * LK_;
    const float* gm = (br ? g_m2 : g_m1) + (b << 11) + row0;
    const float* gl = (br ? g_l2 : g_l1) + (b << 11) + row0;
    float* o = out + (br ? (size_t)B_ * LQ_ * D_ : 0)
                   + ((size_t)((b << 11) + row0)) * D_ + col0;

    const int tid = threadIdx.x;
    if (tid < 128) { s_m[tid] = gm[tid]; s_sc[tid] = 1.f / gl[tid]; }
    __syncthreads();

    const int tr8 = (tid >> 4) << 3;
    const int tc8 = (tid & 15) << 3;
    const int r0 = tid >> 3,  i4 = tid & 7;         // br=0 S mapping
    const int ii0 = tid >> 5, rq4 = (tid & 31) << 2; // br=1 S mapping
    const int kv = tid >> 5,  d4 = tid & 31;         // V mapping

    u64 acc[8][8];
    #pragma unroll
    for (int i = 0; i < 8; i++)
        #pragma unroll
        for (int j = 0; j < 8; j++) acc[i][j] = 0ull;

    float4 pS[4], pV[4];

    auto loadS = [&](int i0) {
        #pragma unroll
        for (int t = 0; t < 4; t++) {
            if (!br) pS[t] = *(const float4*)&Sb[(size_t)(row0 + r0 + 32 * t) * LK_ + i0 + i4 * 4];
            else     pS[t] = *(const float4*)&Sb[(size_t)(i0 + ii0 + 8 * t) * LK_ + row0 + rq4];
        }
    };
    auto loadV = [&](int i0) {
        #pragma unroll
        for (int t = 0; t < 4; t++)
            pV[t] = *(const float4*)&V[(size_t)(i0 + kv + 8 * t) * D_ + col0 + d4 * 4];
    };

    loadS(0); loadV(0);

    for (int i0 = 0; i0 < 2048; i0 += 32) {
        // weights -> ws2 (pairs along inner dim)
        #pragma unroll
        for (int t = 0; t < 4; t++) {
            if (!br) {
                int r = r0 + 32 * t;
                float m = s_m[r];
                uchar4 m4 = *(const uchar4*)&mk[i0 + i4 * 4];
                float w0 = m4.x ? 0.f : __expf(pS[t].x - m);
                float w1 = m4.y ? 0.f : __expf(pS[t].y - m);
                float w2 = m4.z ? 0.f : __expf(pS[t].z - m);
                float w3 = m4.w ? 0.f : __expf(pS[t].w - m);
                ws2[i4 * 2][r]     = make_float2(w0, w1);
                ws2[i4 * 2 + 1][r] = make_float2(w2, w3);
            } else {
                int ii = ii0 + 8 * t;
                bool mm = mk[i0 + ii] != 0;
                float* wp = (float*)&ws2[ii >> 1][0] + (ii & 1);
                float w0 = mm ? 0.f : __expf(pS[t].x - s_m[rq4 + 0]);
                float w1 = mm ? 0.f : __expf(pS[t].y - s_m[rq4 + 1]);
                float w2 = mm ? 0.f : __expf(pS[t].z - s_m[rq4 + 2]);
                float w3 = mm ? 0.f : __expf(pS[t].w - s_m[rq4 + 3]);
                wp[(rq4 + 0) * 2] = w0;
                wp[(rq4 + 1) * 2] = w1;
                wp[(rq4 + 2) * 2] = w2;
                wp[(rq4 + 3) * 2] = w3;
            }
        }
        // V -> vs2 (pairs along inner dim)
        #pragma unroll
        for (int t = 0; t < 4; t++) {
            int k = kv + 8 * t;
            float* vp = (float*)&vs2[k >> 1][0] + (k & 1);
            vp[(d4 * 4 + 0) * 2] = pV[t].x;
            vp[(d4 * 4 + 1) * 2] = pV[t].y;
            vp[(d4 * 4 + 2) * 2] = pV[t].z;
            vp[(d4 * 4 + 3) * 2] = pV[t].w;
        }
        __syncthreads();

        if (i0 + 32 < 2048) { loadS(i0 + 32); loadV(i0 + 32); }

        #pragma unroll
        for (int k2 = 0; k2 < 16; k2++) {
            u64 a2[8], b2[8];
            #pragma unroll
            for (int u = 0; u < 4; u++) {
                ulonglong2 ta = *(const ulonglong2*)&ws2[k2][tr8 + 2 * u];
                a2[2 * u] = ta.x; a2[2 * u + 1] = ta.y;
                ulonglong2 tb = *(const ulonglong2*)&vs2[k2][tc8 + 2 * u];
                b2[2 * u] = tb.x; b2[2 * u + 1] = tb.y;
            }
            #pragma unroll
            for (int i = 0; i < 8; i++)
                #pragma unroll
                for (int j = 0; j < 8; j++)
                    ffma2(acc[i][j], a2[i], b2[j]);
        }
        __syncthreads();
    }

    #pragma unroll
    for (int i = 0; i < 8; i++) {
        int r = tr8 + i;
        float sc = s_sc[r];
        float* orow = &o[(size_t)r * D_ + tc8];
        *(float4*)&orow[0] = make_float4(pairsum(acc[i][0]) * sc, pairsum(acc[i][1]) * sc,
                                         pairsum(acc[i][2]) * sc, pairsum(acc[i][3]) * sc);
        *(float4*)&orow[4] = make_float4(pairsum(acc[i][4]) * sc, pairsum(acc[i][5]) * sc,
                                         pairsum(acc[i][6]) * sc, pairsum(acc[i][7]) * sc);
    }
}

// ---------------------------------------------------------------------------
extern "C" void kernel_launch(void* const* d_in, const int* in_sizes, int n_in,
                              void* d_out, int out_size)
{
    const float* queries = (const float*)d_in[0];
    const float* keys    = (const float*)d_in[1];
    const float* values1 = (const float*)d_in[2];
    const void*  mask1   = d_in[3];
    const float* values2 = (const float*)d_in[4];
    const void*  mask2   = d_in[5];
    const float* Wq      = (const float*)d_in[6];
    const float* Wk      = (const float*)d_in[7];
    const float* scaling = (const float*)d_in[8];
    float* out = (float*)d_out;

    detect_mask_kernel<<<1, 256>>>((const unsigned char*)mask1);
    build_mask_kernel<<<(B_ * LK_ + 255) / 256, 256>>>(mask1, mask2);

    proj_kernel<<<dim3((B_ * LQ_) / 128, 2), 256>>>(queries, keys, Wq, Wk, scaling);

    scores_kernel<<<dim3(LK_ / 128, LQ_ / 128, B_), 256>>>();

    stats1_kernel<<<B_ * LQ_, 256>>>();
    stats2_kernel<<<dim3(LK_ / 64, B_), 256>>>();

    branch_kernel<<<dim3(D_ / 128, 2048 / 128, B_ * 2), 256>>>(values1, values2, out);
}

// round 3
// speedup vs baseline: 1.0007x; 1.0007x over previous
#include <cuda_runtime.h>
#include <cuda_bf16.h>
#include <math.h>

#define B_   8
#define LQ_  2048
#define LK_  2048
#define D_   256
#define H_   128

typedef unsigned long long u64;

// Scratch (device globals: allocation-free per harness rules)
__device__ float g_pq[(size_t)B_ * LQ_ * H_];                 // relu(Q Wq^T)          [B,Lq,H]
__device__ float g_pk[(size_t)B_ * LK_ * H_];                 // relu(K Wk^T)*scaling  [B,Lk,H]
__device__ float g_S [(size_t)B_ * LQ_ * LK_];                // scores                [B,Lq,Lk]
__device__ float g_m1[B_ * LQ_], g_l1[B_ * LQ_];              // branch1 row stats (over k)
__device__ float g_m2[B_ * LK_], g_l2[B_ * LK_];              // branch2 col stats (over q)
__device__ unsigned char g_mask1[B_ * LK_];
__device__ unsigned char g_mask2[B_ * LQ_];
__device__ int g_mask_is_byte;

// packed fp32x2 FMA (SASS FFMA2): d = a*b + d, lanewise on both 32-bit halves
__device__ __forceinline__ void ffma2(u64& d, u64 a, u64 b) {
    asm("fma.rn.f32x2 %0, %1, %2, %0;" : "+l"(d) : "l"(a), "l"(b));
}
__device__ __forceinline__ float pairsum(u64 v) {
    float lo, hi;
    asm("mov.b64 {%0,%1}, %2;" : "=f"(lo), "=f"(hi) : "l"(v));
    return lo + hi;
}

// ---------------------------------------------------------------------------
// Mask dtype canonicalization (bool-as-byte vs int32)
// ---------------------------------------------------------------------------
__global__ void detect_mask_kernel(const unsigned char* m) {
    __shared__ int flag;
    if (threadIdx.x == 0) flag = 0;
    __syncthreads();
    for (int i = threadIdx.x; i < B_ * LK_; i += blockDim.x)
        if ((i & 3) && m[i]) flag = 1;
    __syncthreads();
    if (threadIdx.x == 0) g_mask_is_byte = flag;
}

__global__ void build_mask_kernel(const void* m1, const void* m2) {
    int i = blockIdx.x * blockDim.x + threadIdx.x;
    if (i >= B_ * LK_) return;
    if (g_mask_is_byte) {
        g_mask1[i] = ((const unsigned char*)m1)[i] ? 1 : 0;
        g_mask2[i] = ((const unsigned char*)m2)[i] ? 1 : 0;
    } else {
        g_mask1[i] = ((const int*)m1)[i] ? 1 : 0;
        g_mask2[i] = ((const int*)m2)[i] ? 1 : 0;
    }
}

// ---------------------------------------------------------------------------
// Projections: out[r,h] = relu(sum_d X[r,d] * W[h,d]) (* scaling[h] for pk)
// 128x128 block tile, 8x8 thread tile, f32x2 k-pair accumulators, K=256.
// ---------------------------------------------------------------------------
__global__ void __launch_bounds__(256) proj_kernel(
    const float* __restrict__ Q, const float* __restrict__ K,
    const float* __restrict__ Wq, const float* __restrict__ Wk,
    const float* __restrict__ scaling)
{
    __shared__ float2 As2[16][130];   // (k,k+1) pairs per row
    __shared__ float2 Bs2[16][130];

    const int which = blockIdx.y;
    const float* X = which ? K : Q;
    const float* W = which ? Wk : Wq;
    float* out = which ? g_pk : g_pq;
    const int row0 = blockIdx.x * 128;

    const int tid = threadIdx.x;
    const int tr8 = (tid >> 4) << 3;
    const int tc8 = (tid & 15) << 3;
    const int r0 = tid >> 3, h4 = tid & 7;

    u64 acc[8][8];
    #pragma unroll
    for (int i = 0; i < 8; i++)
        #pragma unroll
        for (int j = 0; j < 8; j++) acc[i][j] = 0ull;

    float4 pa[4], pb[4];
    #pragma unroll
    for (int t = 0; t < 4; t++) {
        pa[t] = *(const float4*)&X[(size_t)(row0 + r0 + 32 * t) * D_ + h4 * 4];
        pb[t] = *(const float4*)&W[(size_t)(r0 + 32 * t) * D_ + h4 * 4];
    }

    for (int k0 = 0; k0 < D_; k0 += 32) {
        #pragma unroll
        for (int t = 0; t < 4; t++) {
            int r = r0 + 32 * t;
            As2[h4 * 2][r]     = make_float2(pa[t].x, pa[t].y);
            As2[h4 * 2 + 1][r] = make_float2(pa[t].z, pa[t].w);
            Bs2[h4 * 2][r]     = make_float2(pb[t].x, pb[t].y);
            Bs2[h4 * 2 + 1][r] = make_float2(pb[t].z, pb[t].w);
        }
        __syncthreads();
        if (k0 + 32 < D_) {
            #pragma unroll
            for (int t = 0; t < 4; t++) {
                pa[t] = *(const float4*)&X[(size_t)(row0 + r0 + 32 * t) * D_ + k0 + 32 + h4 * 4];
                pb[t] = *(const float4*)&W[(size_t)(r0 + 32 * t) * D_ + k0 + 32 + h4 * 4];
            }
        }
        #pragma unroll
        for (int k2 = 0; k2 < 16; k2++) {
            u64 a2[8], b2[8];
            #pragma unroll
            for (int u = 0; u < 4; u++) {
                ulonglong2 ta = *(const ulonglong2*)&As2[k2][tr8 + 2 * u];
                a2[2 * u] = ta.x; a2[2 * u + 1] = ta.y;
                ulonglong2 tb = *(const ulonglong2*)&Bs2[k2][tc8 + 2 * u];
                b2[2 * u] = tb.x; b2[2 * u + 1] = tb.y;
            }
            #pragma unroll
            for (int i = 0; i < 8; i++)
                #pragma unroll
                for (int j = 0; j < 8; j++)
                    ffma2(acc[i][j], a2[i], b2[j]);
        }
        __syncthreads();
    }

    #pragma unroll
    for (int i = 0; i < 8; i++) {
        int r = row0 + tr8 + i;
        float v[8];
        #pragma unroll
        for (int j = 0; j < 8; j++) {
            v[j] = fmaxf(pairsum(acc[i][j]), 0.f);
            if (which) v[j] *= scaling[tc8 + j];
        }
        *(float4*)&out[(size_t)r * H_ + tc8]     = make_float4(v[0], v[1], v[2], v[3]);
        *(float4*)&out[(size_t)r * H_ + tc8 + 4] = make_float4(v[4], v[5], v[6], v[7]);
    }
}

// ---------------------------------------------------------------------------
// scores[b] = pq[b] @ pk[b]^T  (128x128 tile, 8x8 thread tile, f32x2)
// ---------------------------------------------------------------------------
__global__ void __launch_bounds__(256) scores_kernel()
{
    __shared__ float2 As2[16][130];
    __shared__ float2 Bs2[16][130];

    const int b = blockIdx.z;
    const int row0 = blockIdx.y * 128;
    const int col0 = blockIdx.x * 128;
    const float* A  = g_pq + (size_t)b * LQ_ * H_;
    const float* Bm = g_pk + (size_t)b * LK_ * H_;
    float* S = g_S + (size_t)b * LQ_ * LK_;

    const int tid = threadIdx.x;
    const int tr8 = (tid >> 4) << 3;
    const int tc8 = (tid & 15) << 3;
    const int r0 = tid >> 3, h4 = tid & 7;

    u64 acc[8][8];
    #pragma unroll
    for (int i = 0; i < 8; i++)
        #pragma unroll
        for (int j = 0; j < 8; j++) acc[i][j] = 0ull;

    float4 pa[4], pb[4];
    #pragma unroll
    for (int t = 0; t < 4; t++) {
        pa[t] = *(const float4*)&A [(size_t)(row0 + r0 + 32 * t) * H_ + h4 * 4];
        pb[t] = *(const float4*)&Bm[(size_t)(col0 + r0 + 32 * t) * H_ + h4 * 4];
    }

    for (int k0 = 0; k0 < H_; k0 += 32) {
        #pragma unroll
        for (int t = 0; t < 4; t++) {
            int r = r0 + 32 * t;
            As2[h4 * 2][r]     = make_float2(pa[t].x, pa[t].y);
            As2[h4 * 2 + 1][r] = make_float2(pa[t].z, pa[t].w);
            Bs2[h4 * 2][r]     = make_float2(pb[t].x, pb[t].y);
            Bs2[h4 * 2 + 1][r] = make_float2(pb[t].z, pb[t].w);
        }
        __syncthreads();
        if (k0 + 32 < H_) {
            #pragma unroll
            for (int t = 0; t < 4; t++) {
                pa[t] = *(const float4*)&A [(size_t)(row0 + r0 + 32 * t) * H_ + k0 + 32 + h4 * 4];
                pb[t] = *(const float4*)&Bm[(size_t)(col0 + r0 + 32 * t) * H_ + k0 + 32 + h4 * 4];
            }
        }
        #pragma unroll
        for (int k2 = 0; k2 < 16; k2++) {
            u64 a2[8], b2[8];
            #pragma unroll
            for (int u = 0; u < 4; u++) {
                ulonglong2 ta = *(const ulonglong2*)&As2[k2][tr8 + 2 * u];
                a2[2 * u] = ta.x; a2[2 * u + 1] = ta.y;
                ulonglong2 tb = *(const ulonglong2*)&Bs2[k2][tc8 + 2 * u];
                b2[2 * u] = tb.x; b2[2 * u + 1] = tb.y;
            }
            #pragma unroll
            for (int i = 0; i < 8; i++)
                #pragma unroll
                for (int j = 0; j < 8; j++)
                    ffma2(acc[i][j], a2[i], b2[j]);
        }
        __syncthreads();
    }

    #pragma unroll
    for (int i = 0; i < 8; i++) {
        float* orow = &S[(size_t)(row0 + tr8 + i) * LK_ + col0 + tc8];
        *(float4*)&orow[0] = make_float4(pairsum(acc[i][0]), pairsum(acc[i][1]),
                                         pairsum(acc[i][2]), pairsum(acc[i][3]));
        *(float4*)&orow[4] = make_float4(pairsum(acc[i][4]), pairsum(acc[i][5]),
                                         pairsum(acc[i][6]), pairsum(acc[i][7]));
    }
}

// ---------------------------------------------------------------------------
// Branch-1 stats: per (b,q): max & sum-exp over k (masked by g_mask1[b,k])
// ---------------------------------------------------------------------------
__global__ void __launch_bounds__(256) stats1_kernel()
{
    const int row = blockIdx.x;
    const int b = row >> 11;
    const float* Srow = g_S + (size_t)row * LK_;
    const unsigned char* mk = g_mask1 + (b << 11);
    const int tid = threadIdx.x;

    float vals[8];
    float m = -INFINITY;
    #pragma unroll
    for (int i = 0; i < 8; i++) {
        int k = tid + (i << 8);
        float s = Srow[k];
        vals[i] = mk[k] ? -INFINITY : s;
        m = fmaxf(m, vals[i]);
    }

    __shared__ float red[256];
    red[tid] = m;
    __syncthreads();
    for (int off = 128; off > 0; off >>= 1) {
        if (tid < off) red[tid] = fmaxf(red[tid], red[tid + off]);
        __syncthreads();
    }
    m = red[0];
    __syncthreads();

    float l = 0.f;
    #pragma unroll
    for (int i = 0; i < 8; i++) l += __expf(vals[i] - m);
    red[tid] = l;
    __syncthreads();
    for (int off = 128; off > 0; off >>= 1) {
        if (tid < off) red[tid] += red[tid + off];
        __syncthreads();
    }
    if (tid == 0) { g_m1[row] = m; g_l1[row] = red[0]; }
}

// ---------------------------------------------------------------------------
// Branch-2 stats: per (b,k): max & sum-exp over q (masked by g_mask2[b,q]).
// Two clean passes (no online rescale, no divergence).
// ---------------------------------------------------------------------------
__global__ void __launch_bounds__(256) stats2_kernel()
{
    const int b = blockIdx.y;
    const int k0 = blockIdx.x * 64;
    const int tid = threadIdx.x;
    const int kk = tid & 63, qg = tid >> 6;
    const float* Sb = g_S + (size_t)b * LQ_ * LK_;
    const unsigned char* mk = g_mask2 + (b << 11);

    float m = -INFINITY;
    #pragma unroll 8
    for (int q = qg; q < LQ_; q += 4) {
        float s = Sb[(size_t)q * LK_ + k0 + kk];
        m = fmaxf(m, mk[q] ? -INFINITY : s);
    }
    __shared__ float sm[256];
    sm[tid] = m;
    __syncthreads();
    if (tid < 64)
        sm[tid] = fmaxf(fmaxf(sm[tid], sm[tid + 64]), fmaxf(sm[tid + 128], sm[tid + 192]));
    __syncthreads();
    m = sm[kk];

    float l = 0.f;
    #pragma unroll 8
    for (int q = qg; q < LQ_; q += 4) {
        float s = Sb[(size_t)q * LK_ + k0 + kk];
        l += mk[q] ? 0.f : __expf(s - m);
    }
    __shared__ float sl[256];
    sl[tid] = l;
    __syncthreads();
    if (tid < 64) {
        l = sl[tid] + sl[tid + 64] + sl[tid + 128] + sl[tid + 192];
        g_m2[(b << 11) + k0 + tid] = sm[tid];
        g_l2[(b << 11) + k0 + tid] = l;
    }
}

// ---------------------------------------------------------------------------
// Fused softmax-weighted GEMM, both branches, 128x128 tile, f32x2 k-pair.
//   br=0: out1[q,d] = il1[q] * sum_k !m1[k]*exp(S[q,k]-m1[q]) * V1[k,d]
//   br=1: out2[k,d] = il2[k] * sum_q !m2[q]*exp(S[q,k]-m2[k]) * V2[q,d]
// ---------------------------------------------------------------------------
__global__ void __launch_bounds__(256) branch_kernel(
    const float* __restrict__ V1, const float* __restrict__ V2,
    float* __restrict__ out)
{
    __shared__ float2 ws2[16][130];
    __shared__ float2 vs2[16][130];
    __shared__ float s_m[128], s_sc[128];

    const int zz = blockIdx.z;
    const int br = zz & 1, b = zz >> 1;
    const int row0 = blockIdx.y * 128;
    const int col0 = blockIdx.x * 128;

    const float* V = (br ? V2 : V1) + (size_t)b * 2048 * D_;
    const unsigned char* mk = (br ? g_mask2 : g_mask1) + (b << 11);
    const float* Sb = g_S + (size_t)b * LQ_ * LK_;
    const float* gm = (br ? g_m2 : g_m1) + (b << 11) + row0;
    const float* gl = (br ? g_l2 : g_l1) + (b << 11) + row0;
    float* o = out + (br ? (size_t)B_ * LQ_ * D_ : 0)
                   + ((size_t)((b << 11) + row0)) * D_ + col0;

    const int tid = threadIdx.x;
    if (tid < 128) { s_m[tid] = gm[tid]; s_sc[tid] = 1.f / gl[tid]; }
    __syncthreads();

    const int tr8 = (tid >> 4) << 3;
    const int tc8 = (tid & 15) << 3;
    const int r0 = tid >> 3,  i4 = tid & 7;         // br=0 S mapping
    const int ii0 = tid >> 5, rq4 = (tid & 31) << 2; // br=1 S mapping
    const int kv = tid >> 5,  d4 = tid & 31;         // V mapping

    u64 acc[8][8];
    #pragma unroll
    for (int i = 0; i < 8; i++)
        #pragma unroll
        for (int j = 0; j < 8; j++) acc[i][j] = 0ull;

    float4 pS[4], pV[4];

    auto loadS = [&](int i0) {
        #pragma unroll
        for (int t = 0; t < 4; t++) {
            if (!br) pS[t] = *(const float4*)&Sb[(size_t)(row0 + r0 + 32 * t) * LK_ + i0 + i4 * 4];
            else     pS[t] = *(const float4*)&Sb[(size_t)(i0 + ii0 + 8 * t) * LK_ + row0 + rq4];
        }
    };
    auto loadV = [&](int i0) {
        #pragma unroll
        for (int t = 0; t < 4; t++)
            pV[t] = *(const float4*)&V[(size_t)(i0 + kv + 8 * t) * D_ + col0 + d4 * 4];
    };

    loadS(0); loadV(0);

    for (int i0 = 0; i0 < 2048; i0 += 32) {
        // weights -> ws2 (pairs along inner dim)
        #pragma unroll
        for (int t = 0; t < 4; t++) {
            if (!br) {
                int r = r0 + 32 * t;
                float m = s_m[r];
                uchar4 m4 = *(const uchar4*)&mk[i0 + i4 * 4];
                float w0 = m4.x ? 0.f : __expf(pS[t].x - m);
                float w1 = m4.y ? 0.f : __expf(pS[t].y - m);
                float w2 = m4.z ? 0.f : __expf(pS[t].z - m);
                float w3 = m4.w ? 0.f : __expf(pS[t].w - m);
                ws2[i4 * 2][r]     = make_float2(w0, w1);
                ws2[i4 * 2 + 1][r] = make_float2(w2, w3);
            } else {
                int ii = ii0 + 8 * t;
                bool mm = mk[i0 + ii] != 0;
                float* wp = (float*)&ws2[ii >> 1][0] + (ii & 1);
                float w0 = mm ? 0.f : __expf(pS[t].x - s_m[rq4 + 0]);
                float w1 = mm ? 0.f : __expf(pS[t].y - s_m[rq4 + 1]);
                float w2 = mm ? 0.f : __expf(pS[t].z - s_m[rq4 + 2]);
                float w3 = mm ? 0.f : __expf(pS[t].w - s_m[rq4 + 3]);
                wp[(rq4 + 0) * 2] = w0;
                wp[(rq4 + 1) * 2] = w1;
                wp[(rq4 + 2) * 2] = w2;
                wp[(rq4 + 3) * 2] = w3;
            }
        }
        // V -> vs2 (pairs along inner dim)
        #pragma unroll
        for (int t = 0; t < 4; t++) {
            int k = kv + 8 * t;
            float* vp = (float*)&vs2[k >> 1][0] + (k & 1);
            vp[(d4 * 4 + 0) * 2] = pV[t].x;
            vp[(d4 * 4 + 1) * 2] = pV[t].y;
            vp[(d4 * 4 + 2) * 2] = pV[t].z;
            vp[(d4 * 4 + 3) * 2] = pV[t].w;
        }
        __syncthreads();

        if (i0 + 32 < 2048) { loadS(i0 + 32); loadV(i0 + 32); }

        #pragma unroll
        for (int k2 = 0; k2 < 16; k2++) {
            u64 a2[8], b2[8];
            #pragma unroll
            for (int u = 0; u < 4; u++) {
                ulonglong2 ta = *(const ulonglong2*)&ws2[k2][tr8 + 2 * u];
                a2[2 * u] = ta.x; a2[2 * u + 1] = ta.y;
                ulonglong2 tb = *(const ulonglong2*)&vs2[k2][tc8 + 2 * u];
                b2[2 * u] = tb.x; b2[2 * u + 1] = tb.y;
            }
            #pragma unroll
            for (int i = 0; i < 8; i++)
                #pragma unroll
                for (int j = 0; j < 8; j++)
                    ffma2(acc[i][j], a2[i], b2[j]);
        }
        __syncthreads();
    }

    #pragma unroll
    for (int i = 0; i < 8; i++) {
        int r = tr8 + i;
        float sc = s_sc[r];
        float* orow = &o[(size_t)r * D_ + tc8];
        *(float4*)&orow[0] = make_float4(pairsum(acc[i][0]) * sc, pairsum(acc[i][1]) * sc,
                                         pairsum(acc[i][2]) * sc, pairsum(acc[i][3]) * sc);
        *(float4*)&orow[4] = make_float4(pairsum(acc[i][4]) * sc, pairsum(acc[i][5]) * sc,
                                         pairsum(acc[i][6]) * sc, pairsum(acc[i][7]) * sc);
    }
}

// ---------------------------------------------------------------------------
extern "C" void kernel_launch(void* const* d_in, const int* in_sizes, int n_in,
                              void* d_out, int out_size)
{
    const float* queries = (const float*)d_in[0];
    const float* keys    = (const float*)d_in[1];
    const float* values1 = (const float*)d_in[2];
    const void*  mask1   = d_in[3];
    const float* values2 = (const float*)d_in[4];
    const void*  mask2   = d_in[5];
    const float* Wq      = (const float*)d_in[6];
    const float* Wk      = (const float*)d_in[7];
    const float* scaling = (const float*)d_in[8];
    float* out = (float*)d_out;

    detect_mask_kernel<<<1, 256>>>((const unsigned char*)mask1);
    build_mask_kernel<<<(B_ * LK_ + 255) / 256, 256>>>(mask1, mask2);

    proj_kernel<<<dim3((B_ * LQ_) / 128, 2), 256>>>(queries, keys, Wq, Wk, scaling);

    scores_kernel<<<dim3(LK_ / 128, LQ_ / 128, B_), 256>>>();

    stats1_kernel<<<B_ * LQ_, 256>>>();
    stats2_kernel<<<dim3(LK_ / 64, B_), 256>>>();

    branch_kernel<<<dim3(D_ / 128, 2048 / 128, B_ * 2), 256>>>(values1, values2, out);
}

// round 5
// speedup vs baseline: 2.9006x; 2.8985x over previous
#include <cuda_runtime.h>
#include <cuda_bf16.h>
#include <math.h>

#define B_  8
#define L_  2048
#define D_  256
#define H_  128

typedef unsigned int u32;
typedef unsigned long long u64;

// ---------------- device scratch ----------------
__device__ __align__(16) float g_S [(size_t)B_ * L_ * L_];     // [b][q][k]
__device__ __align__(16) float g_St[(size_t)B_ * L_ * L_];     // [b][k][q]
__device__ __align__(16) __nv_bfloat16 g_pq_hi[(size_t)B_ * L_ * H_];
__device__ __align__(16) __nv_bfloat16 g_pq_lo[(size_t)B_ * L_ * H_];
__device__ __align__(16) __nv_bfloat16 g_pk_hi[(size_t)B_ * L_ * H_];
__device__ __align__(16) __nv_bfloat16 g_pk_lo[(size_t)B_ * L_ * H_];
__device__ __align__(16) __nv_bfloat16 g_v1t_hi[(size_t)B_ * D_ * L_];  // [b][d][k]
__device__ __align__(16) __nv_bfloat16 g_v1t_lo[(size_t)B_ * D_ * L_];
__device__ __align__(16) __nv_bfloat16 g_v2t_hi[(size_t)B_ * D_ * L_];  // [b][d][q]
__device__ __align__(16) __nv_bfloat16 g_v2t_lo[(size_t)B_ * D_ * L_];
__device__ float g_m1[B_ * L_], g_l1[B_ * L_];
__device__ float g_m2[B_ * L_], g_l2[B_ * L_];
__device__ unsigned char g_mask1[B_ * L_];
__device__ unsigned char g_mask2[B_ * L_];
__device__ int g_mask_is_byte;

// ---------------- PTX helpers (arch-generic: sm_80+) ----------------
__device__ __forceinline__ u32 smem_u32(const void* p) {
    u32 a;
    asm("{ .reg .u64 t; cvta.to.shared.u64 t, %1; cvt.u32.u64 %0, t; }" : "=r"(a) : "l"(p));
    return a;
}
__device__ __forceinline__ void ldm4(u32* r, u32 addr) {
    asm volatile("ldmatrix.sync.aligned.m8n8.x4.shared.b16 {%0,%1,%2,%3}, [%4];"
        : "=r"(r[0]), "=r"(r[1]), "=r"(r[2]), "=r"(r[3]) : "r"(addr));
}
__device__ __forceinline__ void mma16816(float* c, const u32* a, const u32* b) {
    asm volatile("mma.sync.aligned.m16n8k16.row.col.f32.bf16.bf16.f32 "
        "{%0,%1,%2,%3}, {%4,%5,%6,%7}, {%8,%9}, {%0,%1,%2,%3};"
        : "+f"(c[0]), "+f"(c[1]), "+f"(c[2]), "+f"(c[3])
        : "r"(a[0]), "r"(a[1]), "r"(a[2]), "r"(a[3]), "r"(b[0]), "r"(b[1]));
}
#define CPA16(sm, gp)  asm volatile("cp.async.ca.shared.global [%0], [%1], 16;" :: "r"(sm), "l"(gp))
#define CPA_COMMIT()   asm volatile("cp.async.commit_group;" ::: "memory")
#define CPA_WAIT0()    asm volatile("cp.async.wait_group 0;" ::: "memory")

__device__ __forceinline__ void split_bf(float v, __nv_bfloat16& h, __nv_bfloat16& l) {
    h = __float2bfloat16_rn(v);
    l = __float2bfloat16_rn(v - __bfloat162float(h));
}
__device__ __forceinline__ u64 pack4(__nv_bfloat16 a, __nv_bfloat16 b,
                                     __nv_bfloat16 c, __nv_bfloat16 d) {
    union { __nv_bfloat16 h[4]; u64 u; } x;
    x.h[0] = a; x.h[1] = b; x.h[2] = c; x.h[3] = d;
    return x.u;
}
__device__ __forceinline__ u32 pack2(__nv_bfloat16 a, __nv_bfloat16 b) {
    union { __nv_bfloat16 h[2]; u32 u; } x;
    x.h[0] = a; x.h[1] = b;
    return x.u;
}

// smem tile geometry: 128 rows x 32 bf16, padded row stride 80B (conflict-free ldmatrix)
#define TB    10240        // bytes per tile matrix
#define BUF   (4 * TB)     // Ah | Al | Bh | Bl
#define TOFF  1024         // tiles start (stats arrays live below)
#define GSMEM (TOFF + 2 * BUF)   // 82944

// one K=32 chunk of the 128x128 warp-tiled bf16x3 GEMM
__device__ __forceinline__ void gemm_chunk(u32 sb, int buf, float (&acc)[2][8][4],
                                           int lane, int m0w, int n0w)
{
    const u32 tbase = sb + TOFF + buf * BUF;
    #pragma unroll
    for (int ks = 0; ks < 2; ks++) {
        u32 ah[2][4], al[2][4];
        #pragma unroll
        for (int mi = 0; mi < 2; mi++) {
            u32 a = tbase + (u32)(m0w + mi * 16 + (lane & 15)) * 80 + ks * 32 + (lane >> 4) * 16;
            ldm4(ah[mi], a);
            ldm4(al[mi], a + TB);
        }
        u32 bh[8][2], bl[8][2];
        #pragma unroll
        for (int np = 0; np < 4; np++) {
            int g = lane >> 3, lr = lane & 7;
            u32 a = tbase + 2 * TB
                  + (u32)(n0w + np * 16 + (g >> 1) * 8 + lr) * 80 + ks * 32 + (g & 1) * 16;
            u32 r4[4];
            ldm4(r4, a);
            bh[2 * np][0] = r4[0]; bh[2 * np][1] = r4[1];
            bh[2 * np + 1][0] = r4[2]; bh[2 * np + 1][1] = r4[3];
            ldm4(r4, a + TB);
            bl[2 * np][0] = r4[0]; bl[2 * np][1] = r4[1];
            bl[2 * np + 1][0] = r4[2]; bl[2 * np + 1][1] = r4[3];
        }
        #pragma unroll
        for (int mi = 0; mi < 2; mi++)
            #pragma unroll
            for (int ni = 0; ni < 8; ni++) {
                mma16816(acc[mi][ni], ah[mi], bh[ni]);
                mma16816(acc[mi][ni], ah[mi], bl[ni]);
                mma16816(acc[mi][ni], al[mi], bh[ni]);
            }
    }
}

// ---------------- masks ----------------
__global__ void detect_mask_kernel(const unsigned char* m) {
    __shared__ int flag;
    if (threadIdx.x == 0) flag = 0;
    __syncthreads();
    for (int i = threadIdx.x; i < B_ * L_; i += blockDim.x)
        if ((i & 3) && m[i]) flag = 1;
    __syncthreads();
    if (threadIdx.x == 0) g_mask_is_byte = flag;
}
__global__ void build_mask_kernel(const void* m1, const void* m2) {
    int i = blockIdx.x * blockDim.x + threadIdx.x;
    if (i >= B_ * L_) return;
    if (g_mask_is_byte) {
        g_mask1[i] = ((const unsigned char*)m1)[i] ? 1 : 0;
        g_mask2[i] = ((const unsigned char*)m2)[i] ? 1 : 0;
    } else {
        g_mask1[i] = ((const int*)m1)[i] ? 1 : 0;
        g_mask2[i] = ((const int*)m2)[i] ? 1 : 0;
    }
}

// ---------------- V transpose + hi/lo split ----------------
__global__ void __launch_bounds__(256) vsplit_kernel(
    const float* __restrict__ V1, const float* __restrict__ V2)
{
    __shared__ float ts[64][65];
    const int which = blockIdx.z & 1, b = blockIdx.z >> 1;
    const float* V = (which ? V2 : V1) + (size_t)b * L_ * D_;
    __nv_bfloat16* dh = (which ? g_v2t_hi : g_v1t_hi) + (size_t)b * D_ * L_;
    __nv_bfloat16* dl = (which ? g_v2t_lo : g_v1t_lo) + (size_t)b * D_ * L_;
    const int i0 = blockIdx.x * 64, d0 = blockIdx.y * 64;
    const int tid = threadIdx.x;
    {
        const int r = tid >> 2, c0 = (tid & 3) * 16;
        #pragma unroll
        for (int j = 0; j < 4; j++) {
            float4 v = *(const float4*)&V[(size_t)(i0 + r) * D_ + d0 + c0 + 4 * j];
            ts[r][c0 + 4 * j] = v.x; ts[r][c0 + 4 * j + 1] = v.y;
            ts[r][c0 + 4 * j + 2] = v.z; ts[r][c0 + 4 * j + 3] = v.w;
        }
    }
    __syncthreads();
    {
        const int rd = tid >> 2, cw = (tid & 3) * 16;
        #pragma unroll
        for (int j = 0; j < 4; j++) {
            __nv_bfloat16 h[4], l[4];
            #pragma unroll
            for (int e = 0; e < 4; e++) split_bf(ts[cw + 4 * j + e][rd], h[e], l[e]);
            size_t o = (size_t)(d0 + rd) * L_ + i0 + cw + 4 * j;
            *(u64*)&dh[o] = pack4(h[0], h[1], h[2], h[3]);
            *(u64*)&dl[o] = pack4(l[0], l[1], l[2], l[3]);
        }
    }
}

// ---------------- proj: relu(X W^T)(*scaling) -> bf16 hi/lo ----------------
__global__ void __launch_bounds__(256, 1) proj_kernel(
    const float* __restrict__ Q, const float* __restrict__ K,
    const float* __restrict__ Wq, const float* __restrict__ Wk,
    const float* __restrict__ scaling)
{
    extern __shared__ __align__(16) char smem[];
    const u32 sb = smem_u32(smem);
    const int tid = threadIdx.x, lane = tid & 31, w = tid >> 5;
    const int m0w = (w & 3) * 32, n0w = (w >> 2) * 64;
    const int which = blockIdx.y, row0 = blockIdx.x * 128;
    const float* X  = which ? K : Q;
    const float* Wm = which ? Wk : Wq;
    __nv_bfloat16* oh = which ? g_pk_hi : g_pq_hi;
    __nv_bfloat16* ol = which ? g_pk_lo : g_pq_lo;

    float acc[2][8][4];
    #pragma unroll
    for (int mi = 0; mi < 2; mi++)
        #pragma unroll
        for (int ni = 0; ni < 8; ni++)
            #pragma unroll
            for (int e = 0; e < 4; e++) acc[mi][ni][e] = 0.f;

    const int r_ = tid >> 1, hf = tid & 1;
    char* tp = smem + TOFF;

    for (int c = 0; c < 8; c++) {
        const int k0 = c * 32;
        __syncthreads();
        {
            const float* xr = X  + (size_t)(row0 + r_) * D_ + k0 + hf * 16;
            const float* wr = Wm + (size_t)r_ * D_ + k0 + hf * 16;
            const u32 off = (u32)r_ * 80 + hf * 32;
            #pragma unroll
            for (int j = 0; j < 4; j++) {
                float4 xa = *(const float4*)&xr[4 * j];
                float4 wb = *(const float4*)&wr[4 * j];
                __nv_bfloat16 h[4], l[4];
                split_bf(xa.x, h[0], l[0]); split_bf(xa.y, h[1], l[1]);
                split_bf(xa.z, h[2], l[2]); split_bf(xa.w, h[3], l[3]);
                *(u64*)(tp + off + j * 8)      = pack4(h[0], h[1], h[2], h[3]);
                *(u64*)(tp + TB + off + j * 8) = pack4(l[0], l[1], l[2], l[3]);
                split_bf(wb.x, h[0], l[0]); split_bf(wb.y, h[1], l[1]);
                split_bf(wb.z, h[2], l[2]); split_bf(wb.w, h[3], l[3]);
                *(u64*)(tp + 2 * TB + off + j * 8) = pack4(h[0], h[1], h[2], h[3]);
                *(u64*)(tp + 3 * TB + off + j * 8) = pack4(l[0], l[1], l[2], l[3]);
            }
        }
        __syncthreads();
        gemm_chunk(sb, 0, acc, lane, m0w, n0w);
    }

    #pragma unroll
    for (int mi = 0; mi < 2; mi++) {
        const int rr = row0 + m0w + mi * 16 + (lane >> 2);
        #pragma unroll
        for (int ni = 0; ni < 8; ni++) {
            const int cc = n0w + ni * 8 + 2 * (lane & 3);
            float s0 = 1.f, s1 = 1.f;
            if (which) { s0 = __ldg(&scaling[cc]); s1 = __ldg(&scaling[cc + 1]); }
            float v00 = fmaxf(acc[mi][ni][0], 0.f) * s0;
            float v01 = fmaxf(acc[mi][ni][1], 0.f) * s1;
            float v10 = fmaxf(acc[mi][ni][2], 0.f) * s0;
            float v11 = fmaxf(acc[mi][ni][3], 0.f) * s1;
            __nv_bfloat16 h0, l0, h1, l1;
            split_bf(v00, h0, l0); split_bf(v01, h1, l1);
            *(u32*)&oh[(size_t)rr * H_ + cc] = pack2(h0, h1);
            *(u32*)&ol[(size_t)rr * H_ + cc] = pack2(l0, l1);
            split_bf(v10, h0, l0); split_bf(v11, h1, l1);
            *(u32*)&oh[(size_t)(rr + 8) * H_ + cc] = pack2(h0, h1);
            *(u32*)&ol[(size_t)(rr + 8) * H_ + cc] = pack2(l0, l1);
        }
    }
}

// ---------------- scores: S = pq pk^T (writes S and S^T) ----------------
__global__ void __launch_bounds__(256, 1) scores_kernel()
{
    extern __shared__ __align__(16) char smem[];
    const u32 sb = smem_u32(smem);
    const int tid = threadIdx.x, lane = tid & 31, w = tid >> 5;
    const int m0w = (w & 3) * 32, n0w = (w >> 2) * 64;
    const int b = blockIdx.z, row0 = blockIdx.y * 128, col0 = blockIdx.x * 128;
    const __nv_bfloat16* aqh = g_pq_hi + (size_t)(b * L_ + row0) * H_;
    const __nv_bfloat16* aql = g_pq_lo + (size_t)(b * L_ + row0) * H_;
    const __nv_bfloat16* bkh = g_pk_hi + (size_t)(b * L_ + col0) * H_;
    const __nv_bfloat16* bkl = g_pk_lo + (size_t)(b * L_ + col0) * H_;
    float* S  = g_S  + (size_t)b * L_ * L_;
    float* St = g_St + (size_t)b * L_ * L_;

    float acc[2][8][4];
    #pragma unroll
    for (int mi = 0; mi < 2; mi++)
        #pragma unroll
        for (int ni = 0; ni < 8; ni++)
            #pragma unroll
            for (int e = 0; e < 4; e++) acc[mi][ni][e] = 0.f;

    auto cpAB = [&](int c, int buf) {
        const int k0 = c * 32;
        const u32 base = sb + TOFF + buf * BUF;
        #pragma unroll
        for (int t = 0; t < 2; t++) {
            int idx = tid + t * 256;
            int rr = idx >> 2, seg = idx & 3;
            u32 so = base + (u32)rr * 80 + seg * 16;
            size_t go = (size_t)rr * H_ + k0 + seg * 8;
            CPA16(so,          aqh + go);
            CPA16(so + TB,     aql + go);
            CPA16(so + 2 * TB, bkh + go);
            CPA16(so + 3 * TB, bkl + go);
        }
        CPA_COMMIT();
    };

    cpAB(0, 0);
    CPA_WAIT0();
    __syncthreads();
    for (int c = 0; c < 4; c++) {
        if (c + 1 < 4) cpAB(c + 1, (c + 1) & 1);
        gemm_chunk(sb, c & 1, acc, lane, m0w, n0w);
        if (c + 1 < 4) CPA_WAIT0();
        __syncthreads();
    }

    // epilogue: direct S stores + smem-staged S^T
    float* stg = (float*)(smem + TOFF);     // [128][132]
    #pragma unroll
    for (int mi = 0; mi < 2; mi++) {
        const int rr = m0w + mi * 16 + (lane >> 2);
        float* p0 = S + (size_t)(row0 + rr) * L_ + col0 + n0w + 2 * (lane & 3);
        float* q0 = stg + rr * 132 + n0w + 2 * (lane & 3);
        #pragma unroll
        for (int ni = 0; ni < 8; ni++) {
            *(float2*)(p0 + ni * 8)          = make_float2(acc[mi][ni][0], acc[mi][ni][1]);
            *(float2*)(p0 + 8 * L_ + ni * 8) = make_float2(acc[mi][ni][2], acc[mi][ni][3]);
            *(float2*)(q0 + ni * 8)          = make_float2(acc[mi][ni][0], acc[mi][ni][1]);
            *(float2*)(q0 + 8 * 132 + ni * 8) = make_float2(acc[mi][ni][2], acc[mi][ni][3]);
        }
    }
    __syncthreads();
    {
        const int kk = tid >> 1, qh = tid & 1;
        float* trow = St + (size_t)(col0 + kk) * L_ + row0 + qh * 64;
        #pragma unroll
        for (int j = 0; j < 16; j++) {
            int q = qh * 64 + j * 4;
            *(float4*)&trow[j * 4] = make_float4(
                stg[(q + 0) * 132 + kk], stg[(q + 1) * 132 + kk],
                stg[(q + 2) * 132 + kk], stg[(q + 3) * 132 + kk]);
        }
    }
}

// ---------------- row softmax stats ----------------
__global__ void __launch_bounds__(256) stats_kernel(int which)
{
    const int row = blockIdx.x, b = row >> 11;
    const float* Srow = (which ? g_St : g_S) + (size_t)row * L_;
    const unsigned char* mk = (which ? g_mask2 : g_mask1) + (b << 11);
    float* mo = which ? g_m2 : g_m1;
    float* lo = which ? g_l2 : g_l1;
    const int tid = threadIdx.x;

    float vals[8], m = -INFINITY;
    #pragma unroll
    for (int i = 0; i < 8; i++) {
        int k = tid + (i << 8);
        vals[i] = mk[k] ? -INFINITY : Srow[k];
        m = fmaxf(m, vals[i]);
    }
    __shared__ float red[256];
    red[tid] = m;
    __syncthreads();
    for (int off = 128; off > 0; off >>= 1) {
        if (tid < off) red[tid] = fmaxf(red[tid], red[tid + off]);
        __syncthreads();
    }
    m = red[0];
    __syncthreads();
    float l = 0.f;
    #pragma unroll
    for (int i = 0; i < 8; i++) l += __expf(vals[i] - m);
    red[tid] = l;
    __syncthreads();
    for (int off = 128; off > 0; off >>= 1) {
        if (tid < off) red[tid] += red[tid + off];
        __syncthreads();
    }
    if (tid == 0) { mo[row] = m; lo[row] = red[0]; }
}

// ---------------- branch: out[r,d] = (1/l[r]) sum_i w(r,i) Vt[d,i] ----------------
__global__ void __launch_bounds__(256, 1) branch_kernel(float* __restrict__ out)
{
    extern __shared__ __align__(16) char smem[];
    const u32 sb = smem_u32(smem);
    const int tid = threadIdx.x, lane = tid & 31, w = tid >> 5;
    const int m0w = (w & 3) * 32, n0w = (w >> 2) * 64;
    const int row0 = blockIdx.x * 128, d0 = blockIdx.y * 128;
    const int br = blockIdx.z & 1, b = blockIdx.z >> 1;

    const float* SS = (br ? g_St : g_S) + (size_t)b * L_ * L_;
    const unsigned char* mk = (br ? g_mask2 : g_mask1) + (b << 11);
    const float* gm = (br ? g_m2 : g_m1) + (b << 11) + row0;
    const float* gl = (br ? g_l2 : g_l1) + (b << 11) + row0;
    const __nv_bfloat16* vth = (br ? g_v2t_hi : g_v1t_hi) + (size_t)b * D_ * L_;
    const __nv_bfloat16* vtl = (br ? g_v2t_lo : g_v1t_lo) + (size_t)b * D_ * L_;
    float* ob = out + (br ? (size_t)B_ * L_ * D_ : 0) + (size_t)(b * L_ + row0) * D_ + d0;

    float* s_m  = (float*)(smem);
    float* s_sc = (float*)(smem + 512);
    if (tid < 128) { s_m[tid] = gm[tid]; s_sc[tid] = 1.f / gl[tid]; }
    __syncthreads();

    float acc[2][8][4];
    #pragma unroll
    for (int mi = 0; mi < 2; mi++)
        #pragma unroll
        for (int ni = 0; ni < 8; ni++)
            #pragma unroll
            for (int e = 0; e < 4; e++) acc[mi][ni][e] = 0.f;

    const int r_ = tid >> 1, hf = tid & 1;
    const float mrow = s_m[r_];
    float4 pS[4];
    uint4 pM;

    auto loadS = [&](int c) {
        const int i0 = c * 32;
        const float* srow = SS + (size_t)(row0 + r_) * L_ + i0 + hf * 16;
        pS[0] = *(const float4*)&srow[0];
        pS[1] = *(const float4*)&srow[4];
        pS[2] = *(const float4*)&srow[8];
        pS[3] = *(const float4*)&srow[12];
        pM = *(const uint4*)&mk[i0 + hf * 16];
    };
    auto storeW = [&](int buf) {
        char* base = smem + TOFF + buf * BUF;
        const u32 off = (u32)r_ * 80 + hf * 32;
        union { uint4 v; unsigned char bvec[16]; } mu;
        mu.v = pM;
        #pragma unroll
        for (int j = 0; j < 4; j++) {
            const float* s4 = (const float*)&pS[j];
            __nv_bfloat16 h[4], l[4];
            #pragma unroll
            for (int e = 0; e < 4; e++) {
                float ww = mu.bvec[4 * j + e] ? 0.f : __expf(s4[e] - mrow);
                split_bf(ww, h[e], l[e]);
            }
            *(u64*)(base + off + j * 8)      = pack4(h[0], h[1], h[2], h[3]);
            *(u64*)(base + TB + off + j * 8) = pack4(l[0], l[1], l[2], l[3]);
        }
    };
    auto cpV = [&](int c, int buf) {
        const int i0 = c * 32;
        const u32 base = sb + TOFF + buf * BUF + 2 * TB;
        #pragma unroll
        for (int t = 0; t < 2; t++) {
            int idx = tid + t * 256;
            int rr = idx >> 2, seg = idx & 3;
            u32 so = base + (u32)rr * 80 + seg * 16;
            size_t go = (size_t)(d0 + rr) * L_ + i0 + seg * 8;
            CPA16(so,      vth + go);
            CPA16(so + TB, vtl + go);
        }
        CPA_COMMIT();
    };

    loadS(0); cpV(0, 0); storeW(0);
    CPA_WAIT0();
    __syncthreads();
    for (int c = 0; c < 64; c++) {
        const int buf = c & 1;
        if (c + 1 < 64) { cpV(c + 1, buf ^ 1); loadS(c + 1); }
        gemm_chunk(sb, buf, acc, lane, m0w, n0w);
        if (c + 1 < 64) { storeW(buf ^ 1); CPA_WAIT0(); }
        __syncthreads();
    }

    #pragma unroll
    for (int mi = 0; mi < 2; mi++) {
        const int rr = m0w + mi * 16 + (lane >> 2);
        const float sc0 = s_sc[rr], sc1 = s_sc[rr + 8];
        float* p0 = ob + (size_t)rr * D_ + n0w + 2 * (lane & 3);
        float* p1 = p0 + 8 * D_;
        #pragma unroll
        for (int ni = 0; ni < 8; ni++) {
            *(float2*)(p0 + ni * 8) = make_float2(acc[mi][ni][0] * sc0, acc[mi][ni][1] * sc0);
            *(float2*)(p1 + ni * 8) = make_float2(acc[mi][ni][2] * sc1, acc[mi][ni][3] * sc1);
        }
    }
}

// ---------------------------------------------------------------------------
extern "C" void kernel_launch(void* const* d_in, const int* in_sizes, int n_in,
                              void* d_out, int out_size)
{
    const float* queries = (const float*)d_in[0];
    const float* keys    = (const float*)d_in[1];
    const float* values1 = (const float*)d_in[2];
    const void*  mask1   = d_in[3];
    const float* values2 = (const float*)d_in[4];
    const void*  mask2   = d_in[5];
    const float* Wq      = (const float*)d_in[6];
    const float* Wk      = (const float*)d_in[7];
    const float* scaling = (const float*)d_in[8];
    float* out = (float*)d_out;

    cudaFuncSetAttribute(proj_kernel,   cudaFuncAttributeMaxDynamicSharedMemorySize, GSMEM);
    cudaFuncSetAttribute(scores_kernel, cudaFuncAttributeMaxDynamicSharedMemorySize, GSMEM);
    cudaFuncSetAttribute(branch_kernel, cudaFuncAttributeMaxDynamicSharedMemorySize, GSMEM);

    detect_mask_kernel<<<1, 256>>>((const unsigned char*)mask1);
    build_mask_kernel<<<(B_ * L_ + 255) / 256, 256>>>(mask1, mask2);

    vsplit_kernel<<<dim3(L_ / 64, D_ / 64, B_ * 2), 256>>>(values1, values2);

    proj_kernel<<<dim3((B_ * L_) / 128, 2), 256, GSMEM>>>(queries, keys, Wq, Wk, scaling);

    scores_kernel<<<dim3(L_ / 128, L_ / 128, B_), 256, GSMEM>>>();

    stats_kernel<<<B_ * L_, 256>>>(0);
    stats_kernel<<<B_ * L_, 256>>>(1);

    branch_kernel<<<dim3(L_ / 128, D_ / 128, B_ * 2), 256, GSMEM>>>(out);
}

// round 6
// speedup vs baseline: 3.2539x; 1.1218x over previous
#include <cuda_runtime.h>
#include <cuda_bf16.h>
#include <math.h>

#define B_  8
#define L_  2048
#define D_  256
#define H_  128

typedef unsigned int u32;
typedef unsigned long long u64;

// ---------------- device scratch ----------------
__device__ __align__(16) float g_S [(size_t)B_ * L_ * L_];     // [b][q][k]
__device__ __align__(16) float g_St[(size_t)B_ * L_ * L_];     // [b][k][q]
__device__ __align__(16) __nv_bfloat16 g_w1h[(size_t)B_ * L_ * L_];  // weights br1 [b][q][k]
__device__ __align__(16) __nv_bfloat16 g_w1l[(size_t)B_ * L_ * L_];
__device__ __align__(16) __nv_bfloat16 g_w2h[(size_t)B_ * L_ * L_];  // weights br2 [b][k][q]
__device__ __align__(16) __nv_bfloat16 g_w2l[(size_t)B_ * L_ * L_];
__device__ __align__(16) __nv_bfloat16 g_pq_hi[(size_t)B_ * L_ * H_];
__device__ __align__(16) __nv_bfloat16 g_pq_lo[(size_t)B_ * L_ * H_];
__device__ __align__(16) __nv_bfloat16 g_pk_hi[(size_t)B_ * L_ * H_];
__device__ __align__(16) __nv_bfloat16 g_pk_lo[(size_t)B_ * L_ * H_];
__device__ __align__(16) __nv_bfloat16 g_v1t_hi[(size_t)B_ * D_ * L_];  // [b][d][k]
__device__ __align__(16) __nv_bfloat16 g_v1t_lo[(size_t)B_ * D_ * L_];
__device__ __align__(16) __nv_bfloat16 g_v2t_hi[(size_t)B_ * D_ * L_];  // [b][d][q]
__device__ __align__(16) __nv_bfloat16 g_v2t_lo[(size_t)B_ * D_ * L_];
__device__ float g_m1[B_ * L_], g_l1[B_ * L_];
__device__ float g_m2[B_ * L_], g_l2[B_ * L_];
__device__ unsigned char g_mask1[B_ * L_];
__device__ unsigned char g_mask2[B_ * L_];
__device__ int g_mask_is_byte;

// ---------------- PTX helpers (arch-generic: sm_80+) ----------------
__device__ __forceinline__ u32 smem_u32(const void* p) {
    u32 a;
    asm("{ .reg .u64 t; cvta.to.shared.u64 t, %1; cvt.u32.u64 %0, t; }" : "=r"(a) : "l"(p));
    return a;
}
__device__ __forceinline__ void ldm4(u32* r, u32 addr) {
    asm volatile("ldmatrix.sync.aligned.m8n8.x4.shared.b16 {%0,%1,%2,%3}, [%4];"
        : "=r"(r[0]), "=r"(r[1]), "=r"(r[2]), "=r"(r[3]) : "r"(addr));
}
__device__ __forceinline__ void mma16816(float* c, const u32* a, const u32* b) {
    asm volatile("mma.sync.aligned.m16n8k16.row.col.f32.bf16.bf16.f32 "
        "{%0,%1,%2,%3}, {%4,%5,%6,%7}, {%8,%9}, {%0,%1,%2,%3};"
        : "+f"(c[0]), "+f"(c[1]), "+f"(c[2]), "+f"(c[3])
        : "r"(a[0]), "r"(a[1]), "r"(a[2]), "r"(a[3]), "r"(b[0]), "r"(b[1]));
}
#define CPA16(sm, gp)  asm volatile("cp.async.ca.shared.global [%0], [%1], 16;" :: "r"(sm), "l"(gp))
#define CPA_COMMIT()   asm volatile("cp.async.commit_group;" ::: "memory")
template<int N> __device__ __forceinline__ void cpa_wait() {
    asm volatile("cp.async.wait_group %0;" :: "n"(N) : "memory");
}

__device__ __forceinline__ void split_bf(float v, __nv_bfloat16& h, __nv_bfloat16& l) {
    h = __float2bfloat16_rn(v);
    l = __float2bfloat16_rn(v - __bfloat162float(h));
}
__device__ __forceinline__ u64 pack4(__nv_bfloat16 a, __nv_bfloat16 b,
                                     __nv_bfloat16 c, __nv_bfloat16 d) {
    union { __nv_bfloat16 h[4]; u64 u; } x;
    x.h[0] = a; x.h[1] = b; x.h[2] = c; x.h[3] = d;
    return x.u;
}
__device__ __forceinline__ u32 pack2(__nv_bfloat16 a, __nv_bfloat16 b) {
    union { __nv_bfloat16 h[2]; u32 u; } x;
    x.h[0] = a; x.h[1] = b;
    return x.u;
}

// smem tile geometry: 128 rows x 32 bf16, padded row stride 80B
#define TB    10240        // bytes per tile matrix
#define STG   (4 * TB)     // Ah | Al | Bh | Bl per pipeline stage
#define NSTG  4
#define TOFF  1024
#define GSMEM (TOFF + NSTG * STG)   // 164864
#define PSMEM (TOFF + STG)          // proj: single stage

// one K=32 chunk of the 128x128 warp-tiled bf16x3 GEMM
__device__ __forceinline__ void gemm_chunk(u32 sb, int stage, float (&acc)[2][8][4],
                                           int lane, int m0w, int n0w)
{
    const u32 tbase = sb + TOFF + stage * STG;
    #pragma unroll
    for (int ks = 0; ks < 2; ks++) {
        u32 ah[2][4], al[2][4];
        #pragma unroll
        for (int mi = 0; mi < 2; mi++) {
            u32 a = tbase + (u32)(m0w + mi * 16 + (lane & 15)) * 80 + ks * 32 + (lane >> 4) * 16;
            ldm4(ah[mi], a);
            ldm4(al[mi], a + TB);
        }
        u32 bh[8][2], bl[8][2];
        #pragma unroll
        for (int np = 0; np < 4; np++) {
            int g = lane >> 3, lr = lane & 7;
            u32 a = tbase + 2 * TB
                  + (u32)(n0w + np * 16 + (g >> 1) * 8 + lr) * 80 + ks * 32 + (g & 1) * 16;
            u32 r4[4];
            ldm4(r4, a);
            bh[2 * np][0] = r4[0]; bh[2 * np][1] = r4[1];
            bh[2 * np + 1][0] = r4[2]; bh[2 * np + 1][1] = r4[3];
            ldm4(r4, a + TB);
            bl[2 * np][0] = r4[0]; bl[2 * np][1] = r4[1];
            bl[2 * np + 1][0] = r4[2]; bl[2 * np + 1][1] = r4[3];
        }
        #pragma unroll
        for (int mi = 0; mi < 2; mi++)
            #pragma unroll
            for (int ni = 0; ni < 8; ni++) {
                mma16816(acc[mi][ni], ah[mi], bh[ni]);
                mma16816(acc[mi][ni], ah[mi], bl[ni]);
                mma16816(acc[mi][ni], al[mi], bh[ni]);
            }
    }
}

// ---------------- masks ----------------
__global__ void detect_mask_kernel(const unsigned char* m) {
    __shared__ int flag;
    if (threadIdx.x == 0) flag = 0;
    __syncthreads();
    for (int i = threadIdx.x; i < B_ * L_; i += blockDim.x)
        if ((i & 3) && m[i]) flag = 1;
    __syncthreads();
    if (threadIdx.x == 0) g_mask_is_byte = flag;
}
__global__ void build_mask_kernel(const void* m1, const void* m2) {
    int i = blockIdx.x * blockDim.x + threadIdx.x;
    if (i >= B_ * L_) return;
    if (g_mask_is_byte) {
        g_mask1[i] = ((const unsigned char*)m1)[i] ? 1 : 0;
        g_mask2[i] = ((const unsigned char*)m2)[i] ? 1 : 0;
    } else {
        g_mask1[i] = ((const int*)m1)[i] ? 1 : 0;
        g_mask2[i] = ((const int*)m2)[i] ? 1 : 0;
    }
}

// ---------------- V transpose + hi/lo split ----------------
__global__ void __launch_bounds__(256) vsplit_kernel(
    const float* __restrict__ V1, const float* __restrict__ V2)
{
    __shared__ float ts[64][65];
    const int which = blockIdx.z & 1, b = blockIdx.z >> 1;
    const float* V = (which ? V2 : V1) + (size_t)b * L_ * D_;
    __nv_bfloat16* dh = (which ? g_v2t_hi : g_v1t_hi) + (size_t)b * D_ * L_;
    __nv_bfloat16* dl = (which ? g_v2t_lo : g_v1t_lo) + (size_t)b * D_ * L_;
    const int i0 = blockIdx.x * 64, d0 = blockIdx.y * 64;
    const int tid = threadIdx.x;
    {
        const int r = tid >> 2, c0 = (tid & 3) * 16;
        #pragma unroll
        for (int j = 0; j < 4; j++) {
            float4 v = *(const float4*)&V[(size_t)(i0 + r) * D_ + d0 + c0 + 4 * j];
            ts[r][c0 + 4 * j] = v.x; ts[r][c0 + 4 * j + 1] = v.y;
            ts[r][c0 + 4 * j + 2] = v.z; ts[r][c0 + 4 * j + 3] = v.w;
        }
    }
    __syncthreads();
    {
        const int rd = tid >> 2, cw = (tid & 3) * 16;
        #pragma unroll
        for (int j = 0; j < 4; j++) {
            __nv_bfloat16 h[4], l[4];
            #pragma unroll
            for (int e = 0; e < 4; e++) split_bf(ts[cw + 4 * j + e][rd], h[e], l[e]);
            size_t o = (size_t)(d0 + rd) * L_ + i0 + cw + 4 * j;
            *(u64*)&dh[o] = pack4(h[0], h[1], h[2], h[3]);
            *(u64*)&dl[o] = pack4(l[0], l[1], l[2], l[3]);
        }
    }
}

// ---------------- proj: relu(X W^T)(*scaling) -> bf16 hi/lo ----------------
__global__ void __launch_bounds__(256, 1) proj_kernel(
    const float* __restrict__ Q, const float* __restrict__ K,
    const float* __restrict__ Wq, const float* __restrict__ Wk,
    const float* __restrict__ scaling)
{
    extern __shared__ __align__(16) char smem[];
    const u32 sb = smem_u32(smem);
    const int tid = threadIdx.x, lane = tid & 31, w = tid >> 5;
    const int m0w = (w & 3) * 32, n0w = (w >> 2) * 64;
    const int which = blockIdx.y, row0 = blockIdx.x * 128;
    const float* X  = which ? K : Q;
    const float* Wm = which ? Wk : Wq;
    __nv_bfloat16* oh = which ? g_pk_hi : g_pq_hi;
    __nv_bfloat16* ol = which ? g_pk_lo : g_pq_lo;

    float acc[2][8][4];
    #pragma unroll
    for (int mi = 0; mi < 2; mi++)
        #pragma unroll
        for (int ni = 0; ni < 8; ni++)
            #pragma unroll
            for (int e = 0; e < 4; e++) acc[mi][ni][e] = 0.f;

    const int r_ = tid >> 1, hf = tid & 1;
    char* tp = smem + TOFF;

    for (int c = 0; c < 8; c++) {
        const int k0 = c * 32;
        __syncthreads();
        {
            const float* xr = X  + (size_t)(row0 + r_) * D_ + k0 + hf * 16;
            const float* wr = Wm + (size_t)r_ * D_ + k0 + hf * 16;
            const u32 off = (u32)r_ * 80 + hf * 32;
            #pragma unroll
            for (int j = 0; j < 4; j++) {
                float4 xa = *(const float4*)&xr[4 * j];
                float4 wb = *(const float4*)&wr[4 * j];
                __nv_bfloat16 h[4], l[4];
                split_bf(xa.x, h[0], l[0]); split_bf(xa.y, h[1], l[1]);
                split_bf(xa.z, h[2], l[2]); split_bf(xa.w, h[3], l[3]);
                *(u64*)(tp + off + j * 8)      = pack4(h[0], h[1], h[2], h[3]);
                *(u64*)(tp + TB + off + j * 8) = pack4(l[0], l[1], l[2], l[3]);
                split_bf(wb.x, h[0], l[0]); split_bf(wb.y, h[1], l[1]);
                split_bf(wb.z, h[2], l[2]); split_bf(wb.w, h[3], l[3]);
                *(u64*)(tp + 2 * TB + off + j * 8) = pack4(h[0], h[1], h[2], h[3]);
                *(u64*)(tp + 3 * TB + off + j * 8) = pack4(l[0], l[1], l[2], l[3]);
            }
        }
        __syncthreads();
        gemm_chunk(sb, 0, acc, lane, m0w, n0w);
    }

    #pragma unroll
    for (int mi = 0; mi < 2; mi++) {
        const int rr = row0 + m0w + mi * 16 + (lane >> 2);
        #pragma unroll
        for (int ni = 0; ni < 8; ni++) {
            const int cc = n0w + ni * 8 + 2 * (lane & 3);
            float s0 = 1.f, s1 = 1.f;
            if (which) { s0 = __ldg(&scaling[cc]); s1 = __ldg(&scaling[cc + 1]); }
            float v00 = fmaxf(acc[mi][ni][0], 0.f) * s0;
            float v01 = fmaxf(acc[mi][ni][1], 0.f) * s1;
            float v10 = fmaxf(acc[mi][ni][2], 0.f) * s0;
            float v11 = fmaxf(acc[mi][ni][3], 0.f) * s1;
            __nv_bfloat16 h0, l0, h1, l1;
            split_bf(v00, h0, l0); split_bf(v01, h1, l1);
            *(u32*)&oh[(size_t)rr * H_ + cc] = pack2(h0, h1);
            *(u32*)&ol[(size_t)rr * H_ + cc] = pack2(l0, l1);
            split_bf(v10, h0, l0); split_bf(v11, h1, l1);
            *(u32*)&oh[(size_t)(rr + 8) * H_ + cc] = pack2(h0, h1);
            *(u32*)&ol[(size_t)(rr + 8) * H_ + cc] = pack2(l0, l1);
        }
    }
}

// ---------------- scores: S = pq pk^T (writes S and S^T) ----------------
__global__ void __launch_bounds__(256, 1) scores_kernel()
{
    extern __shared__ __align__(16) char smem[];
    const u32 sb = smem_u32(smem);
    const int tid = threadIdx.x, lane = tid & 31, w = tid >> 5;
    const int m0w = (w & 3) * 32, n0w = (w >> 2) * 64;
    const int b = blockIdx.z, row0 = blockIdx.y * 128, col0 = blockIdx.x * 128;
    const __nv_bfloat16* aqh = g_pq_hi + (size_t)(b * L_ + row0) * H_;
    const __nv_bfloat16* aql = g_pq_lo + (size_t)(b * L_ + row0) * H_;
    const __nv_bfloat16* bkh = g_pk_hi + (size_t)(b * L_ + col0) * H_;
    const __nv_bfloat16* bkl = g_pk_lo + (size_t)(b * L_ + col0) * H_;
    float* S  = g_S  + (size_t)b * L_ * L_;
    float* St = g_St + (size_t)b * L_ * L_;

    float acc[2][8][4];
    #pragma unroll
    for (int mi = 0; mi < 2; mi++)
        #pragma unroll
        for (int ni = 0; ni < 8; ni++)
            #pragma unroll
            for (int e = 0; e < 4; e++) acc[mi][ni][e] = 0.f;

    auto cpAB = [&](int c, int stage) {
        const int k0 = c * 32;
        const u32 base = sb + TOFF + stage * STG;
        #pragma unroll
        for (int t = 0; t < 2; t++) {
            int idx = tid + t * 256;
            int rr = idx >> 2, seg = idx & 3;
            u32 so = base + (u32)rr * 80 + seg * 16;
            size_t go = (size_t)rr * H_ + k0 + seg * 8;
            CPA16(so,          aqh + go);
            CPA16(so + TB,     aql + go);
            CPA16(so + 2 * TB, bkh + go);
            CPA16(so + 3 * TB, bkl + go);
        }
        CPA_COMMIT();
    };

    // full prefetch of all 4 K-chunks
    cpAB(0, 0); cpAB(1, 1); cpAB(2, 2); cpAB(3, 3);
    #pragma unroll
    for (int c = 0; c < 4; c++) {
        if      (c == 0) cpa_wait<3>();
        else if (c == 1) cpa_wait<2>();
        else if (c == 2) cpa_wait<1>();
        else             cpa_wait<0>();
        __syncthreads();
        gemm_chunk(sb, c, acc, lane, m0w, n0w);
    }
    __syncthreads();

    // epilogue: direct S stores + smem-staged S^T
    float* stg = (float*)(smem + TOFF);     // [128][132]
    #pragma unroll
    for (int mi = 0; mi < 2; mi++) {
        const int rr = m0w + mi * 16 + (lane >> 2);
        float* p0 = S + (size_t)(row0 + rr) * L_ + col0 + n0w + 2 * (lane & 3);
        float* q0 = stg + rr * 132 + n0w + 2 * (lane & 3);
        #pragma unroll
        for (int ni = 0; ni < 8; ni++) {
            *(float2*)(p0 + ni * 8)          = make_float2(acc[mi][ni][0], acc[mi][ni][1]);
            *(float2*)(p0 + 8 * L_ + ni * 8) = make_float2(acc[mi][ni][2], acc[mi][ni][3]);
            *(float2*)(q0 + ni * 8)          = make_float2(acc[mi][ni][0], acc[mi][ni][1]);
            *(float2*)(q0 + 8 * 132 + ni * 8) = make_float2(acc[mi][ni][2], acc[mi][ni][3]);
        }
    }
    __syncthreads();
    {
        const int kk = tid >> 1, qh = tid & 1;
        float* trow = St + (size_t)(col0 + kk) * L_ + row0 + qh * 64;
        #pragma unroll
        for (int j = 0; j < 16; j++) {
            int q = qh * 64 + j * 4;
            *(float4*)&trow[j * 4] = make_float4(
                stg[(q + 0) * 132 + kk], stg[(q + 1) * 132 + kk],
                stg[(q + 2) * 132 + kk], stg[(q + 3) * 132 + kk]);
        }
    }
}

// ---------------- stats + weight materialization ----------------
// per row: m, l over masked S row; then W = split(exp(s - m)) written once.
__global__ void __launch_bounds__(256) stats_kernel()
{
    const int which = blockIdx.y;
    const int row = blockIdx.x, b = row >> 11;
    const float* Srow = (which ? g_St : g_S) + (size_t)row * L_;
    const unsigned char* mk = (which ? g_mask2 : g_mask1) + (b << 11);
    float* mo = which ? g_m2 : g_m1;
    float* lo = which ? g_l2 : g_l1;
    __nv_bfloat16* Wh = (which ? g_w2h : g_w1h) + (size_t)row * L_;
    __nv_bfloat16* Wl = (which ? g_w2l : g_w1l) + (size_t)row * L_;
    const int tid = threadIdx.x;

    float vals[8], m = -INFINITY;
    #pragma unroll
    for (int i = 0; i < 8; i++) {
        int k = tid + (i << 8);
        vals[i] = mk[k] ? -INFINITY : Srow[k];
        m = fmaxf(m, vals[i]);
    }
    __shared__ float red[256];
    red[tid] = m;
    __syncthreads();
    for (int off = 128; off > 0; off >>= 1) {
        if (tid < off) red[tid] = fmaxf(red[tid], red[tid + off]);
        __syncthreads();
    }
    m = red[0];
    __syncthreads();
    float l = 0.f;
    float wv[8];
    #pragma unroll
    for (int i = 0; i < 8; i++) { wv[i] = __expf(vals[i] - m); l += wv[i]; }
    red[tid] = l;
    __syncthreads();
    for (int off = 128; off > 0; off >>= 1) {
        if (tid < off) red[tid] += red[tid + off];
        __syncthreads();
    }
    if (tid == 0) { mo[row] = m; lo[row] = red[0]; }
    #pragma unroll
    for (int i = 0; i < 8; i++) {
        int k = tid + (i << 8);
        __nv_bfloat16 h, lb;
        split_bf(wv[i], h, lb);
        Wh[k] = h; Wl[k] = lb;
    }
}

// ---------------- branch: pure cp.async bf16x3 GEMM, out = (1/l) W @ Vt^T ----------------
__global__ void __launch_bounds__(256, 1) branch_kernel(float* __restrict__ out)
{
    extern __shared__ __align__(16) char smem[];
    const u32 sb = smem_u32(smem);
    const int tid = threadIdx.x, lane = tid & 31, w = tid >> 5;
    const int m0w = (w & 3) * 32, n0w = (w >> 2) * 64;
    const int row0 = blockIdx.x * 128, d0 = blockIdx.y * 128;
    const int br = blockIdx.z & 1, b = blockIdx.z >> 1;

    const __nv_bfloat16* wh = (br ? g_w2h : g_w1h) + (size_t)(b * L_ + row0) * L_;
    const __nv_bfloat16* wl = (br ? g_w2l : g_w1l) + (size_t)(b * L_ + row0) * L_;
    const __nv_bfloat16* vth = (br ? g_v2t_hi : g_v1t_hi) + (size_t)b * D_ * L_ + (size_t)d0 * L_;
    const __nv_bfloat16* vtl = (br ? g_v2t_lo : g_v1t_lo) + (size_t)b * D_ * L_ + (size_t)d0 * L_;
    const float* gl = (br ? g_l2 : g_l1) + (b << 11) + row0;
    float* ob = out + (br ? (size_t)B_ * L_ * D_ : 0) + (size_t)(b * L_ + row0) * D_ + d0;

    float* s_sc = (float*)(smem);
    if (tid < 128) s_sc[tid] = 1.f / gl[tid];
    __syncthreads();

    float acc[2][8][4];
    #pragma unroll
    for (int mi = 0; mi < 2; mi++)
        #pragma unroll
        for (int ni = 0; ni < 8; ni++)
            #pragma unroll
            for (int e = 0; e < 4; e++) acc[mi][ni][e] = 0.f;

    auto cpc = [&](int c, int stage) {
        const int i0 = c * 32;
        const u32 base = sb + TOFF + stage * STG;
        #pragma unroll
        for (int t = 0; t < 2; t++) {
            int idx = tid + t * 256;
            int rr = idx >> 2, seg = idx & 3;
            u32 so = base + (u32)rr * 80 + seg * 16;
            size_t ga = (size_t)rr * L_ + i0 + seg * 8;
            CPA16(so,          wh  + ga);
            CPA16(so + TB,     wl  + ga);
            CPA16(so + 2 * TB, vth + ga);
            CPA16(so + 3 * TB, vtl + ga);
        }
    };

    cpc(0, 0); CPA_COMMIT();
    cpc(1, 1); CPA_COMMIT();
    cpc(2, 2); CPA_COMMIT();
    cpc(3, 3); CPA_COMMIT();

    for (int c = 0; c < 64; c++) {
        cpa_wait<3>();
        __syncthreads();
        gemm_chunk(sb, c & 3, acc, lane, m0w, n0w);
        __syncthreads();
        if (c + 4 < 64) cpc(c + 4, (c + 4) & 3);
        CPA_COMMIT();   // unconditional: keeps group count uniform for wait<3>
    }

    #pragma unroll
    for (int mi = 0; mi < 2; mi++) {
        const int rr = m0w + mi * 16 + (lane >> 2);
        const float sc0 = s_sc[rr], sc1 = s_sc[rr + 8];
        float* p0 = ob + (size_t)rr * D_ + n0w + 2 * (lane & 3);
        float* p1 = p0 + 8 * D_;
        #pragma unroll
        for (int ni = 0; ni < 8; ni++) {
            *(float2*)(p0 + ni * 8) = make_float2(acc[mi][ni][0] * sc0, acc[mi][ni][1] * sc0);
            *(float2*)(p1 + ni * 8) = make_float2(acc[mi][ni][2] * sc1, acc[mi][ni][3] * sc1);
        }
    }
}

// ---------------------------------------------------------------------------
extern "C" void kernel_launch(void* const* d_in, const int* in_sizes, int n_in,
                              void* d_out, int out_size)
{
    const float* queries = (const float*)d_in[0];
    const float* keys    = (const float*)d_in[1];
    const float* values1 = (const float*)d_in[2];
    const void*  mask1   = d_in[3];
    const float* values2 = (const float*)d_in[4];
    const void*  mask2   = d_in[5];
    const float* Wq      = (const float*)d_in[6];
    const float* Wk      = (const float*)d_in[7];
    const float* scaling = (const float*)d_in[8];
    float* out = (float*)d_out;

    cudaFuncSetAttribute(proj_kernel,   cudaFuncAttributeMaxDynamicSharedMemorySize, PSMEM);
    cudaFuncSetAttribute(scores_kernel, cudaFuncAttributeMaxDynamicSharedMemorySize, GSMEM);
    cudaFuncSetAttribute(branch_kernel, cudaFuncAttributeMaxDynamicSharedMemorySize, GSMEM);

    detect_mask_kernel<<<1, 256>>>((const unsigned char*)mask1);
    build_mask_kernel<<<(B_ * L_ + 255) / 256, 256>>>(mask1, mask2);

    vsplit_kernel<<<dim3(L_ / 64, D_ / 64, B_ * 2), 256>>>(values1, values2);

    proj_kernel<<<dim3((B_ * L_) / 128, 2), 256, PSMEM>>>(queries, keys, Wq, Wk, scaling);

    scores_kernel<<<dim3(L_ / 128, L_ / 128, B_), 256, GSMEM>>>();

    stats_kernel<<<dim3(B_ * L_, 2), 256>>>();

    branch_kernel<<<dim3(L_ / 128, D_ / 128, B_ * 2), 256, GSMEM>>>(out);
}

// round 7
// speedup vs baseline: 3.6745x; 1.1292x over previous
#include <cuda_runtime.h>
#include <cuda_bf16.h>
#include <cuda_fp16.h>
#include <math.h>

#define B_  8
#define L_  2048
#define D_  256
#define H_  128

typedef unsigned int u32;
typedef unsigned long long u64;

// ---------------- device scratch ----------------
__device__ __align__(16) float g_S [(size_t)B_ * L_ * L_];     // [b][q][k]
__device__ __align__(16) float g_St[(size_t)B_ * L_ * L_];     // [b][k][q]
__device__ __align__(16) __half g_w1[(size_t)B_ * L_ * L_];    // weights br1 [b][q][k] (fp16)
__device__ __align__(16) __half g_w2[(size_t)B_ * L_ * L_];    // weights br2 [b][k][q]
__device__ __align__(16) __nv_bfloat16 g_pq_hi[(size_t)B_ * L_ * H_];
__device__ __align__(16) __nv_bfloat16 g_pq_lo[(size_t)B_ * L_ * H_];
__device__ __align__(16) __nv_bfloat16 g_pk_hi[(size_t)B_ * L_ * H_];
__device__ __align__(16) __nv_bfloat16 g_pk_lo[(size_t)B_ * L_ * H_];
__device__ __align__(16) __half g_v1t_hi[(size_t)B_ * D_ * L_];  // V^T fp16 hi/lo [b][d][k]
__device__ __align__(16) __half g_v1t_lo[(size_t)B_ * D_ * L_];
__device__ __align__(16) __half g_v2t_hi[(size_t)B_ * D_ * L_];
__device__ __align__(16) __half g_v2t_lo[(size_t)B_ * D_ * L_];
__device__ float g_m1[B_ * L_], g_l1[B_ * L_];
__device__ float g_m2[B_ * L_], g_l2[B_ * L_];
__device__ unsigned char g_mask1[B_ * L_];
__device__ unsigned char g_mask2[B_ * L_];
__device__ int g_mask_is_byte;

// ---------------- PTX helpers ----------------
__device__ __forceinline__ u32 smem_u32(const void* p) {
    u32 a;
    asm("{ .reg .u64 t; cvta.to.shared.u64 t, %1; cvt.u32.u64 %0, t; }" : "=r"(a) : "l"(p));
    return a;
}
__device__ __forceinline__ void ldm4(u32* r, u32 addr) {
    asm volatile("ldmatrix.sync.aligned.m8n8.x4.shared.b16 {%0,%1,%2,%3}, [%4];"
        : "=r"(r[0]), "=r"(r[1]), "=r"(r[2]), "=r"(r[3]) : "r"(addr));
}
__device__ __forceinline__ void mma_bf(float* c, const u32* a, const u32* b) {
    asm volatile("mma.sync.aligned.m16n8k16.row.col.f32.bf16.bf16.f32 "
        "{%0,%1,%2,%3}, {%4,%5,%6,%7}, {%8,%9}, {%0,%1,%2,%3};"
        : "+f"(c[0]), "+f"(c[1]), "+f"(c[2]), "+f"(c[3])
        : "r"(a[0]), "r"(a[1]), "r"(a[2]), "r"(a[3]), "r"(b[0]), "r"(b[1]));
}
__device__ __forceinline__ void mma_fp(float* c, const u32* a, const u32* b) {
    asm volatile("mma.sync.aligned.m16n8k16.row.col.f32.f16.f16.f32 "
        "{%0,%1,%2,%3}, {%4,%5,%6,%7}, {%8,%9}, {%0,%1,%2,%3};"
        : "+f"(c[0]), "+f"(c[1]), "+f"(c[2]), "+f"(c[3])
        : "r"(a[0]), "r"(a[1]), "r"(a[2]), "r"(a[3]), "r"(b[0]), "r"(b[1]));
}
#define CPA16(sm, gp)  asm volatile("cp.async.ca.shared.global [%0], [%1], 16;" :: "r"(sm), "l"(gp))
#define CPA_COMMIT()   asm volatile("cp.async.commit_group;" ::: "memory")
template<int N> __device__ __forceinline__ void cpa_wait() {
    asm volatile("cp.async.wait_group %0;" :: "n"(N) : "memory");
}

__device__ __forceinline__ void split_bf(float v, __nv_bfloat16& h, __nv_bfloat16& l) {
    h = __float2bfloat16_rn(v);
    l = __float2bfloat16_rn(v - __bfloat162float(h));
}
__device__ __forceinline__ void split_hf(float v, __half& h, __half& l) {
    h = __float2half_rn(v);
    l = __float2half_rn(v - __half2float(h));
}
__device__ __forceinline__ u64 pack4(__nv_bfloat16 a, __nv_bfloat16 b,
                                     __nv_bfloat16 c, __nv_bfloat16 d) {
    union { __nv_bfloat16 h[4]; u64 u; } x;
    x.h[0] = a; x.h[1] = b; x.h[2] = c; x.h[3] = d;
    return x.u;
}
__device__ __forceinline__ u64 pack4h(__half a, __half b, __half c, __half d) {
    union { __half h[4]; u64 u; } x;
    x.h[0] = a; x.h[1] = b; x.h[2] = c; x.h[3] = d;
    return x.u;
}
__device__ __forceinline__ u32 pack2(__nv_bfloat16 a, __nv_bfloat16 b) {
    union { __nv_bfloat16 h[2]; u32 u; } x;
    x.h[0] = a; x.h[1] = b;
    return x.u;
}

// tile geometry: rows x 32 halves, padded row stride 80B
#define TB    10240                  // 128 rows x 80B
#define STG4  (4 * TB)               // scores/proj stage: Ah|Al|Bh|Bl (128-row B)
#define TOFF  1024
#define SSMEM (TOFF + 4 * STG4)      // scores: 164864
#define PSMEM (TOFF + STG4)          // proj single stage
#define BSTG  (5 * TB)               // branch stage: A(128) | Bh(256) | Bl(256) = 51200
#define BSMEM (TOFF + 4 * BSTG)      // 205824

// bf16x3 chunk (proj/scores): 8 warps, warp tile 32x64 over 128x128
__device__ __forceinline__ void gemm_chunk(u32 sb, int stage, float (&acc)[2][8][4],
                                           int lane, int m0w, int n0w)
{
    const u32 tbase = sb + TOFF + stage * STG4;
    #pragma unroll
    for (int ks = 0; ks < 2; ks++) {
        u32 ah[2][4], al[2][4];
        #pragma unroll
        for (int mi = 0; mi < 2; mi++) {
            u32 a = tbase + (u32)(m0w + mi * 16 + (lane & 15)) * 80 + ks * 32 + (lane >> 4) * 16;
            ldm4(ah[mi], a);
            ldm4(al[mi], a + TB);
        }
        u32 bh[8][2], bl[8][2];
        #pragma unroll
        for (int np = 0; np < 4; np++) {
            int g = lane >> 3, lr = lane & 7;
            u32 a = tbase + 2 * TB
                  + (u32)(n0w + np * 16 + (g >> 1) * 8 + lr) * 80 + ks * 32 + (g & 1) * 16;
            u32 r4[4];
            ldm4(r4, a);
            bh[2 * np][0] = r4[0]; bh[2 * np][1] = r4[1];
            bh[2 * np + 1][0] = r4[2]; bh[2 * np + 1][1] = r4[3];
            ldm4(r4, a + TB);
            bl[2 * np][0] = r4[0]; bl[2 * np][1] = r4[1];
            bl[2 * np + 1][0] = r4[2]; bl[2 * np + 1][1] = r4[3];
        }
        #pragma unroll
        for (int mi = 0; mi < 2; mi++)
            #pragma unroll
            for (int ni = 0; ni < 8; ni++) {
                mma_bf(acc[mi][ni], ah[mi], bh[ni]);
                mma_bf(acc[mi][ni], ah[mi], bl[ni]);
                mma_bf(acc[mi][ni], al[mi], bh[ni]);
            }
    }
}

// fp16 2-mma chunk (branch): 16 warps, warp tile 32x64 over 128x256
__device__ __forceinline__ void gemm_chunk_f16(u32 sb, int stage, float (&acc)[2][8][4],
                                               int lane, int m0w, int n0w)
{
    const u32 tbase = sb + TOFF + stage * BSTG;
    #pragma unroll
    for (int ks = 0; ks < 2; ks++) {
        u32 aw[2][4];
        #pragma unroll
        for (int mi = 0; mi < 2; mi++) {
            u32 a = tbase + (u32)(m0w + mi * 16 + (lane & 15)) * 80 + ks * 32 + (lane >> 4) * 16;
            ldm4(aw[mi], a);
        }
        u32 bh[8][2], bl[8][2];
        #pragma unroll
        for (int np = 0; np < 4; np++) {
            int g = lane >> 3, lr = lane & 7;
            u32 a = tbase + TB
                  + (u32)(n0w + np * 16 + (g >> 1) * 8 + lr) * 80 + ks * 32 + (g & 1) * 16;
            u32 r4[4];
            ldm4(r4, a);
            bh[2 * np][0] = r4[0]; bh[2 * np][1] = r4[1];
            bh[2 * np + 1][0] = r4[2]; bh[2 * np + 1][1] = r4[3];
            ldm4(r4, a + 2 * TB);
            bl[2 * np][0] = r4[0]; bl[2 * np][1] = r4[1];
            bl[2 * np + 1][0] = r4[2]; bl[2 * np + 1][1] = r4[3];
        }
        #pragma unroll
        for (int mi = 0; mi < 2; mi++)
            #pragma unroll
            for (int ni = 0; ni < 8; ni++) {
                mma_fp(acc[mi][ni], aw[mi], bh[ni]);
                mma_fp(acc[mi][ni], aw[mi], bl[ni]);
            }
    }
}

// ---------------- masks ----------------
__global__ void detect_mask_kernel(const unsigned char* m) {
    __shared__ int flag;
    if (threadIdx.x == 0) flag = 0;
    __syncthreads();
    for (int i = threadIdx.x; i < B_ * L_; i += blockDim.x)
        if ((i & 3) && m[i]) flag = 1;
    __syncthreads();
    if (threadIdx.x == 0) g_mask_is_byte = flag;
}
__global__ void build_mask_kernel(const void* m1, const void* m2) {
    int i = blockIdx.x * blockDim.x + threadIdx.x;
    if (i >= B_ * L_) return;
    if (g_mask_is_byte) {
        g_mask1[i] = ((const unsigned char*)m1)[i] ? 1 : 0;
        g_mask2[i] = ((const unsigned char*)m2)[i] ? 1 : 0;
    } else {
        g_mask1[i] = ((const int*)m1)[i] ? 1 : 0;
        g_mask2[i] = ((const int*)m2)[i] ? 1 : 0;
    }
}

// ---------------- V transpose + fp16 hi/lo split ----------------
__global__ void __launch_bounds__(256) vsplit_kernel(
    const float* __restrict__ V1, const float* __restrict__ V2)
{
    __shared__ float ts[64][65];
    const int which = blockIdx.z & 1, b = blockIdx.z >> 1;
    const float* V = (which ? V2 : V1) + (size_t)b * L_ * D_;
    __half* dh = (which ? g_v2t_hi : g_v1t_hi) + (size_t)b * D_ * L_;
    __half* dl = (which ? g_v2t_lo : g_v1t_lo) + (size_t)b * D_ * L_;
    const int i0 = blockIdx.x * 64, d0 = blockIdx.y * 64;
    const int tid = threadIdx.x;
    {
        const int r = tid >> 2, c0 = (tid & 3) * 16;
        #pragma unroll
        for (int j = 0; j < 4; j++) {
            float4 v = *(const float4*)&V[(size_t)(i0 + r) * D_ + d0 + c0 + 4 * j];
            ts[r][c0 + 4 * j] = v.x; ts[r][c0 + 4 * j + 1] = v.y;
            ts[r][c0 + 4 * j + 2] = v.z; ts[r][c0 + 4 * j + 3] = v.w;
        }
    }
    __syncthreads();
    {
        const int rd = tid >> 2, cw = (tid & 3) * 16;
        #pragma unroll
        for (int j = 0; j < 4; j++) {
            __half h[4], l[4];
            #pragma unroll
            for (int e = 0; e < 4; e++) split_hf(ts[cw + 4 * j + e][rd], h[e], l[e]);
            size_t o = (size_t)(d0 + rd) * L_ + i0 + cw + 4 * j;
            *(u64*)&dh[o] = pack4h(h[0], h[1], h[2], h[3]);
            *(u64*)&dl[o] = pack4h(l[0], l[1], l[2], l[3]);
        }
    }
}

// ---------------- proj: relu(X W^T)(*scaling) -> bf16 hi/lo ----------------
__global__ void __launch_bounds__(256, 1) proj_kernel(
    const float* __restrict__ Q, const float* __restrict__ K,
    const float* __restrict__ Wq, const float* __restrict__ Wk,
    const float* __restrict__ scaling)
{
    extern __shared__ __align__(16) char smem[];
    const u32 sb = smem_u32(smem);
    const int tid = threadIdx.x, lane = tid & 31, w = tid >> 5;
    const int m0w = (w & 3) * 32, n0w = (w >> 2) * 64;
    const int which = blockIdx.y, row0 = blockIdx.x * 128;
    const float* X  = which ? K : Q;
    const float* Wm = which ? Wk : Wq;
    __nv_bfloat16* oh = which ? g_pk_hi : g_pq_hi;
    __nv_bfloat16* ol = which ? g_pk_lo : g_pq_lo;

    float acc[2][8][4];
    #pragma unroll
    for (int mi = 0; mi < 2; mi++)
        #pragma unroll
        for (int ni = 0; ni < 8; ni++)
            #pragma unroll
            for (int e = 0; e < 4; e++) acc[mi][ni][e] = 0.f;

    const int r_ = tid >> 1, hf = tid & 1;
    char* tp = smem + TOFF;

    for (int c = 0; c < 8; c++) {
        const int k0 = c * 32;
        __syncthreads();
        {
            const float* xr = X  + (size_t)(row0 + r_) * D_ + k0 + hf * 16;
            const float* wr = Wm + (size_t)r_ * D_ + k0 + hf * 16;
            const u32 off = (u32)r_ * 80 + hf * 32;
            #pragma unroll
            for (int j = 0; j < 4; j++) {
                float4 xa = *(const float4*)&xr[4 * j];
                float4 wb = *(const float4*)&wr[4 * j];
                __nv_bfloat16 h[4], l[4];
                split_bf(xa.x, h[0], l[0]); split_bf(xa.y, h[1], l[1]);
                split_bf(xa.z, h[2], l[2]); split_bf(xa.w, h[3], l[3]);
                *(u64*)(tp + off + j * 8)      = pack4(h[0], h[1], h[2], h[3]);
                *(u64*)(tp + TB + off + j * 8) = pack4(l[0], l[1], l[2], l[3]);
                split_bf(wb.x, h[0], l[0]); split_bf(wb.y, h[1], l[1]);
                split_bf(wb.z, h[2], l[2]); split_bf(wb.w, h[3], l[3]);
                *(u64*)(tp + 2 * TB + off + j * 8) = pack4(h[0], h[1], h[2], h[3]);
                *(u64*)(tp + 3 * TB + off + j * 8) = pack4(l[0], l[1], l[2], l[3]);
            }
        }
        __syncthreads();
        gemm_chunk(sb, 0, acc, lane, m0w, n0w);
    }

    #pragma unroll
    for (int mi = 0; mi < 2; mi++) {
        const int rr = row0 + m0w + mi * 16 + (lane >> 2);
        #pragma unroll
        for (int ni = 0; ni < 8; ni++) {
            const int cc = n0w + ni * 8 + 2 * (lane & 3);
            float s0 = 1.f, s1 = 1.f;
            if (which) { s0 = __ldg(&scaling[cc]); s1 = __ldg(&scaling[cc + 1]); }
            float v00 = fmaxf(acc[mi][ni][0], 0.f) * s0;
            float v01 = fmaxf(acc[mi][ni][1], 0.f) * s1;
            float v10 = fmaxf(acc[mi][ni][2], 0.f) * s0;
            float v11 = fmaxf(acc[mi][ni][3], 0.f) * s1;
            __nv_bfloat16 h0, l0, h1, l1;
            split_bf(v00, h0, l0); split_bf(v01, h1, l1);
            *(u32*)&oh[(size_t)rr * H_ + cc] = pack2(h0, h1);
            *(u32*)&ol[(size_t)rr * H_ + cc] = pack2(l0, l1);
            split_bf(v10, h0, l0); split_bf(v11, h1, l1);
            *(u32*)&oh[(size_t)(rr + 8) * H_ + cc] = pack2(h0, h1);
            *(u32*)&ol[(size_t)(rr + 8) * H_ + cc] = pack2(l0, l1);
        }
    }
}

// ---------------- scores: S = pq pk^T (writes S and S^T) ----------------
__global__ void __launch_bounds__(256, 1) scores_kernel()
{
    extern __shared__ __align__(16) char smem[];
    const u32 sb = smem_u32(smem);
    const int tid = threadIdx.x, lane = tid & 31, w = tid >> 5;
    const int m0w = (w & 3) * 32, n0w = (w >> 2) * 64;
    const int b = blockIdx.z, row0 = blockIdx.y * 128, col0 = blockIdx.x * 128;
    const __nv_bfloat16* aqh = g_pq_hi + (size_t)(b * L_ + row0) * H_;
    const __nv_bfloat16* aql = g_pq_lo + (size_t)(b * L_ + row0) * H_;
    const __nv_bfloat16* bkh = g_pk_hi + (size_t)(b * L_ + col0) * H_;
    const __nv_bfloat16* bkl = g_pk_lo + (size_t)(b * L_ + col0) * H_;
    float* S  = g_S  + (size_t)b * L_ * L_;
    float* St = g_St + (size_t)b * L_ * L_;

    float acc[2][8][4];
    #pragma unroll
    for (int mi = 0; mi < 2; mi++)
        #pragma unroll
        for (int ni = 0; ni < 8; ni++)
            #pragma unroll
            for (int e = 0; e < 4; e++) acc[mi][ni][e] = 0.f;

    auto cpAB = [&](int c, int stage) {
        const int k0 = c * 32;
        const u32 base = sb + TOFF + stage * STG4;
        #pragma unroll
        for (int t = 0; t < 2; t++) {
            int idx = tid + t * 256;
            int rr = idx >> 2, seg = idx & 3;
            u32 so = base + (u32)rr * 80 + seg * 16;
            size_t go = (size_t)rr * H_ + k0 + seg * 8;
            CPA16(so,          aqh + go);
            CPA16(so + TB,     aql + go);
            CPA16(so + 2 * TB, bkh + go);
            CPA16(so + 3 * TB, bkl + go);
        }
        CPA_COMMIT();
    };

    cpAB(0, 0); cpAB(1, 1); cpAB(2, 2); cpAB(3, 3);
    #pragma unroll
    for (int c = 0; c < 4; c++) {
        if      (c == 0) cpa_wait<3>();
        else if (c == 1) cpa_wait<2>();
        else if (c == 2) cpa_wait<1>();
        else             cpa_wait<0>();
        __syncthreads();
        gemm_chunk(sb, c, acc, lane, m0w, n0w);
    }
    __syncthreads();

    float* stg = (float*)(smem + TOFF);     // [128][132]
    #pragma unroll
    for (int mi = 0; mi < 2; mi++) {
        const int rr = m0w + mi * 16 + (lane >> 2);
        float* p0 = S + (size_t)(row0 + rr) * L_ + col0 + n0w + 2 * (lane & 3);
        float* q0 = stg + rr * 132 + n0w + 2 * (lane & 3);
        #pragma unroll
        for (int ni = 0; ni < 8; ni++) {
            *(float2*)(p0 + ni * 8)          = make_float2(acc[mi][ni][0], acc[mi][ni][1]);
            *(float2*)(p0 + 8 * L_ + ni * 8) = make_float2(acc[mi][ni][2], acc[mi][ni][3]);
            *(float2*)(q0 + ni * 8)          = make_float2(acc[mi][ni][0], acc[mi][ni][1]);
            *(float2*)(q0 + 8 * 132 + ni * 8) = make_float2(acc[mi][ni][2], acc[mi][ni][3]);
        }
    }
    __syncthreads();
    {
        const int kk = tid >> 1, qh = tid & 1;
        float* trow = St + (size_t)(col0 + kk) * L_ + row0 + qh * 64;
        #pragma unroll
        for (int j = 0; j < 16; j++) {
            int q = qh * 64 + j * 4;
            *(float4*)&trow[j * 4] = make_float4(
                stg[(q + 0) * 132 + kk], stg[(q + 1) * 132 + kk],
                stg[(q + 2) * 132 + kk], stg[(q + 3) * 132 + kk]);
        }
    }
}

// ---------------- stats + fp16 weight materialization ----------------
__global__ void __launch_bounds__(256) stats_kernel()
{
    const int which = blockIdx.y;
    const int row = blockIdx.x, b = row >> 11;
    const float* Srow = (which ? g_St : g_S) + (size_t)row * L_;
    const unsigned char* mk = (which ? g_mask2 : g_mask1) + (b << 11);
    float* mo = which ? g_m2 : g_m1;
    float* lo = which ? g_l2 : g_l1;
    __half* W = (which ? g_w2 : g_w1) + (size_t)row * L_;
    const int tid = threadIdx.x;

    float vals[8], m = -INFINITY;
    #pragma unroll
    for (int i = 0; i < 8; i++) {
        int k = tid + (i << 8);
        vals[i] = mk[k] ? -INFINITY : Srow[k];
        m = fmaxf(m, vals[i]);
    }
    __shared__ float red[256];
    red[tid] = m;
    __syncthreads();
    for (int off = 128; off > 0; off >>= 1) {
        if (tid < off) red[tid] = fmaxf(red[tid], red[tid + off]);
        __syncthreads();
    }
    m = red[0];
    __syncthreads();
    float l = 0.f, wv[8];
    #pragma unroll
    for (int i = 0; i < 8; i++) { wv[i] = __expf(vals[i] - m); l += wv[i]; }
    red[tid] = l;
    __syncthreads();
    for (int off = 128; off > 0; off >>= 1) {
        if (tid < off) red[tid] += red[tid + off];
        __syncthreads();
    }
    if (tid == 0) { mo[row] = m; lo[row] = red[0]; }
    #pragma unroll
    for (int i = 0; i < 8; i++)
        W[tid + (i << 8)] = __float2half_rn(wv[i]);
}

// ---------------- branch: fp16 GEMM, 128x256 full-D tile, 512 thr ----------------
__global__ void __launch_bounds__(512, 1) branch_kernel(float* __restrict__ out)
{
    extern __shared__ __align__(16) char smem[];
    const u32 sb = smem_u32(smem);
    const int tid = threadIdx.x, lane = tid & 31, w = tid >> 5;
    const int m0w = (w & 3) * 32, n0w = (w >> 2) * 64;   // 16 warps: 4x4
    const int row0 = blockIdx.x * 128;
    const int br = blockIdx.z & 1, b = blockIdx.z >> 1;

    const __half* wf  = (br ? g_w2 : g_w1) + (size_t)(b * L_ + row0) * L_;
    const __half* vth = (br ? g_v2t_hi : g_v1t_hi) + (size_t)b * D_ * L_;
    const __half* vtl = (br ? g_v2t_lo : g_v1t_lo) + (size_t)b * D_ * L_;
    const float* gl = (br ? g_l2 : g_l1) + (b << 11) + row0;
    float* ob = out + (br ? (size_t)B_ * L_ * D_ : 0) + (size_t)(b * L_ + row0) * D_;

    float* s_sc = (float*)(smem);
    if (tid < 128) s_sc[tid] = 1.f / gl[tid];
    __syncthreads();

    float acc[2][8][4];
    #pragma unroll
    for (int mi = 0; mi < 2; mi++)
        #pragma unroll
        for (int ni = 0; ni < 8; ni++)
            #pragma unroll
            for (int e = 0; e < 4; e++) acc[mi][ni][e] = 0.f;

    auto cpc = [&](int c, int stage) {
        const int i0 = c * 32;
        const u32 base = sb + TOFF + stage * BSTG;
        {   // A: W 128 rows x 64B
            int rr = tid >> 2, seg = tid & 3;
            CPA16(base + (u32)rr * 80 + seg * 16, wf + (size_t)rr * L_ + i0 + seg * 8);
        }
        #pragma unroll
        for (int t = 0; t < 2; t++) {   // B: Vt 256 rows x 64B, hi & lo
            int idx = tid + t * 512;
            int rr = idx >> 2, seg = idx & 3;
            u32 so = base + TB + (u32)rr * 80 + seg * 16;
            size_t ga = (size_t)rr * L_ + i0 + seg * 8;
            CPA16(so,          vth + ga);
            CPA16(so + 2 * TB, vtl + ga);
        }
    };

    cpc(0, 0); CPA_COMMIT();
    cpc(1, 1); CPA_COMMIT();
    cpc(2, 2); CPA_COMMIT();
    cpc(3, 3); CPA_COMMIT();

    for (int c = 0; c < 64; c++) {
        cpa_wait<3>();
        __syncthreads();
        gemm_chunk_f16(sb, c & 3, acc, lane, m0w, n0w);
        __syncthreads();
        if (c + 4 < 64) cpc(c + 4, (c + 4) & 3);
        CPA_COMMIT();
    }

    #pragma unroll
    for (int mi = 0; mi < 2; mi++) {
        const int rr = m0w + mi * 16 + (lane >> 2);
        const float sc0 = s_sc[rr], sc1 = s_sc[rr + 8];
        float* p0 = ob + (size_t)rr * D_ + n0w + 2 * (lane & 3);
        float* p1 = p0 + 8 * D_;
        #pragma unroll
        for (int ni = 0; ni < 8; ni++) {
            *(float2*)(p0 + ni * 8) = make_float2(acc[mi][ni][0] * sc0, acc[mi][ni][1] * sc0);
            *(float2*)(p1 + ni * 8) = make_float2(acc[mi][ni][2] * sc1, acc[mi][ni][3] * sc1);
        }
    }
}

// ---------------------------------------------------------------------------
extern "C" void kernel_launch(void* const* d_in, const int* in_sizes, int n_in,
                              void* d_out, int out_size)
{
    const float* queries = (const float*)d_in[0];
    const float* keys    = (const float*)d_in[1];
    const float* values1 = (const float*)d_in[2];
    const void*  mask1   = d_in[3];
    const float* values2 = (const float*)d_in[4];
    const void*  mask2   = d_in[5];
    const float* Wq      = (const float*)d_in[6];
    const float* Wk      = (const float*)d_in[7];
    const float* scaling = (const float*)d_in[8];
    float* out = (float*)d_out;

    cudaFuncSetAttribute(proj_kernel,   cudaFuncAttributeMaxDynamicSharedMemorySize, PSMEM);
    cudaFuncSetAttribute(scores_kernel, cudaFuncAttributeMaxDynamicSharedMemorySize, SSMEM);
    cudaFuncSetAttribute(branch_kernel, cudaFuncAttributeMaxDynamicSharedMemorySize, BSMEM);

    detect_mask_kernel<<<1, 256>>>((const unsigned char*)mask1);
    build_mask_kernel<<<(B_ * L_ + 255) / 256, 256>>>(mask1, mask2);

    vsplit_kernel<<<dim3(L_ / 64, D_ / 64, B_ * 2), 256>>>(values1, values2);

    proj_kernel<<<dim3((B_ * L_) / 128, 2), 256, PSMEM>>>(queries, keys, Wq, Wk, scaling);

    scores_kernel<<<dim3(L_ / 128, L_ / 128, B_), 256, SSMEM>>>();

    stats_kernel<<<dim3(B_ * L_, 2), 256>>>();

    branch_kernel<<<dim3(L_ / 128, 1, B_ * 2), 512, BSMEM>>>(out);
}